// round 7
// baseline (speedup 1.0000x reference)
#include <cuda_runtime.h>
#include <cuda_bf16.h>
#include <math.h>
#include <stdint.h>

// Problem constants
#define B_    4
#define T_    2048
#define DM_   2048
#define H_    16
#define HKV_  4
#define D_    128
#define M_    (B_*T_)      // 8192 tokens
#define NQ_   (H_*D_)      // 2048
#define NKV_  (HKV_*D_)    // 512

// Scratch (device globals: allocation-free per harness rules)
__device__ float g_q  [M_*NQ_];
__device__ float g_k  [M_*NKV_];
__device__ float g_v  [M_*NKV_];
__device__ float g_att[M_*NQ_];       // packed bf16 hi|lo u32 (flash output)
__device__ float g_xr [M_*DM_];       // packed bf16 hi|lo u32
__device__ float g_wq [NQ_*DM_];      // packed
__device__ float g_wk [NKV_*DM_];     // packed
__device__ float g_wv [NKV_*DM_];     // packed
__device__ float g_wo [DM_*NQ_];      // packed
__device__ float g_rope[T_*64*2];

// ---------------------------------------------------------------------------
// Helpers
// ---------------------------------------------------------------------------
__device__ __forceinline__ uint32_t smem_u32(const void* p) {
    uint32_t a;
    asm("{ .reg .u64 t; cvta.to.shared.u64 t, %1; cvt.u32.u64 %0, t; }" : "=r"(a) : "l"(p));
    return a;
}
__device__ __forceinline__ float rna_tf32(float v) {
    uint32_t b;
    asm("cvt.rna.tf32.f32 %0, %1;" : "=r"(b) : "f"(v));
    return __uint_as_float(b);
}
__device__ __forceinline__ uint32_t rna_tf32_u(float v) {
    uint32_t b;
    asm("cvt.rna.tf32.f32 %0, %1;" : "=r"(b) : "f"(v));
    return b;
}
// Split fp32 into bf16 hi (high 16 bits) | bf16 lo (low 16 bits)
__device__ __forceinline__ uint32_t pack_split(float v) {
    __nv_bfloat16 h = __float2bfloat16(v);
    float hf = __bfloat162float(h);
    __nv_bfloat16 l = __float2bfloat16(v - hf);
    return ((uint32_t)__bfloat16_as_ushort(h) << 16) | (uint32_t)__bfloat16_as_ushort(l);
}
// From two packed elements (k even, k odd): bf16x2 of the hi / lo parts
__device__ __forceinline__ uint32_t prmt_hi(uint32_t a, uint32_t b) {
    uint32_t d; asm("prmt.b32 %0,%1,%2,0x7632;" : "=r"(d) : "r"(a), "r"(b)); return d;
}
__device__ __forceinline__ uint32_t prmt_lo(uint32_t a, uint32_t b) {
    uint32_t d; asm("prmt.b32 %0,%1,%2,0x5410;" : "=r"(d) : "r"(a), "r"(b)); return d;
}

#define CP_ASYNC16(dst, src) \
    asm volatile("cp.async.cg.shared.global [%0], [%1], 16;" :: "r"(dst), "l"(src) : "memory")
#define CP_COMMIT()  asm volatile("cp.async.commit_group;" ::: "memory")
#define CP_WAIT(n)   asm volatile("cp.async.wait_group %0;" :: "n"(n) : "memory")

// mma.sync tf32 m16n8k8 (flash) and bf16 m16n8k16 (GEMMs) — both sm_80+ portable
#define MMA_TF32(c, a, b) \
    asm volatile("mma.sync.aligned.m16n8k8.row.col.f32.tf32.tf32.f32 " \
        "{%0,%1,%2,%3}, {%4,%5,%6,%7}, {%8,%9}, {%0,%1,%2,%3};" \
        : "+f"((c)[0]), "+f"((c)[1]), "+f"((c)[2]), "+f"((c)[3]) \
        : "r"((a)[0]), "r"((a)[1]), "r"((a)[2]), "r"((a)[3]), \
          "r"((b)[0]), "r"((b)[1]))
#define MMA_BF16(c, a, b) \
    asm volatile("mma.sync.aligned.m16n8k16.row.col.f32.bf16.bf16.f32 " \
        "{%0,%1,%2,%3}, {%4,%5,%6,%7}, {%8,%9}, {%0,%1,%2,%3};" \
        : "+f"((c)[0]), "+f"((c)[1]), "+f"((c)[2]), "+f"((c)[3]) \
        : "r"((a)[0]), "r"((a)[1]), "r"((a)[2]), "r"((a)[3]), \
          "r"((b)[0]), "r"((b)[1]))

// ---------------------------------------------------------------------------
// Prepass: fp32 -> packed bf16 hi|lo
// ---------------------------------------------------------------------------
__global__ void split_bf16_kernel(const float* __restrict__ in, uint32_t* __restrict__ out, long n4) {
    long i = (blockIdx.x * (long)blockDim.x + threadIdx.x);
    if (i >= n4) return;
    float4 v = ((const float4*)in)[i];
    uint4 o;
    o.x = pack_split(v.x); o.y = pack_split(v.y);
    o.z = pack_split(v.z); o.w = pack_split(v.w);
    ((uint4*)out)[i] = o;
}

__global__ void rope_table_kernel(float* __restrict__ tab) {
    int idx = blockIdx.x * blockDim.x + threadIdx.x;
    if (idx >= T_ * 64) return;
    int t = idx >> 6, f = idx & 63;
    double invf = exp(-((double)f / 64.0) * log(10000.0));
    float ang = (float)t * (float)invf;
    tab[idx*2 + 0] = (float)cos((double)ang);
    tab[idx*2 + 1] = (float)sin((double)ang);
}

// ---------------------------------------------------------------------------
// Split-bf16 GEMM: C[M,N] = A[M,K] @ W[N,K]^T, inputs packed bf16 hi|lo u32.
// Per k16 slab: 3 bf16 m16n8k16 MMAs (ah*bh + ah*bl + al*bh) — ~2^-17 accurate.
// CTA 128x128x32, 8 warps (2m x 4n, 64x32 warp tiles), 2 CTAs/SM.
// Same loader/footprint as the fp32 version (1 u32 per element, stride 40).
// FUSE: per-head RMSNorm + rotary via smem C-stage (fp32 out for flash).
// ---------------------------------------------------------------------------
#define STAGE_F 10240
#define STAGE_B (STAGE_F*4)

template<bool FUSE, bool ROUND>
__global__ __launch_bounds__(256, 2)
void tc_gemm(const uint32_t* __restrict__ A, const uint32_t* __restrict__ W,
             float* __restrict__ C, int M, int N, int K,
             const float* __restrict__ rope)
{
    extern __shared__ float smf[];
    uint32_t* smu = (uint32_t*)smf;
    const uint32_t sbase = smem_u32(smf);

    const int tid  = threadIdx.x;
    const int lane = tid & 31;
    const int wid  = tid >> 5;
    const int warp_m = wid >> 2;
    const int warp_n = wid & 3;
    const int g  = lane >> 2;
    const int q4 = lane & 3;
    const int bx = blockIdx.x, by = blockIdx.y;

    const uint32_t* Ab = A + (size_t)(by * 128) * K;
    const uint32_t* Wb = W + (size_t)(bx * 128) * K;

    float acc[4][4][4];
    #pragma unroll
    for (int mi = 0; mi < 4; ++mi)
        #pragma unroll
        for (int ni = 0; ni < 4; ++ni)
            #pragma unroll
            for (int e = 0; e < 4; ++e) acc[mi][ni][e] = 0.f;

    const int KT = K >> 5;

    auto load_stage = [&](int s, int kt) {
        uint32_t aS = sbase + s * STAGE_B;
        uint32_t bS = aS + 20480;
        const uint32_t* ap = Ab + kt * 32;
        const uint32_t* wp = Wb + kt * 32;
        #pragma unroll
        for (int it = 0; it < 4; ++it) {
            int idx = it * 256 + tid;
            int row = idx >> 3, seg = idx & 7;
            uint32_t so = (uint32_t)row * 160 + (uint32_t)seg * 16;
            CP_ASYNC16(aS + so, ap + (size_t)row * K + seg * 4);
            CP_ASYNC16(bS + so, wp + (size_t)row * K + seg * 4);
        }
    };

    load_stage(0, 0);
    CP_COMMIT();

    for (int kt = 0; kt < KT; ++kt) {
        const int cur = kt & 1;
        if (kt + 1 < KT) {
            load_stage(cur ^ 1, kt + 1);
            CP_COMMIT();
            CP_WAIT(1);
        } else {
            CP_WAIT(0);
        }
        __syncthreads();

        const uint32_t* As_ = smu + cur * STAGE_F + warp_m * (64 * 40);
        const uint32_t* Bs_ = smu + cur * STAGE_F + 5120 + warp_n * (32 * 40);

        #pragma unroll
        for (int ks = 0; ks < 2; ++ks) {           // two k16 slabs per chunk
            const int cb = ks * 16 + 2 * q4;
            uint32_t bh[4][2], bl[4][2];
            #pragma unroll
            for (int ni = 0; ni < 4; ++ni) {
                const uint32_t* bp = Bs_ + (ni * 8 + g) * 40 + cb;
                uint2 e0 = *(const uint2*)bp;          // k = cb, cb+1
                uint2 e1 = *(const uint2*)(bp + 8);    // k = cb+8, cb+9
                bh[ni][0] = prmt_hi(e0.x, e0.y); bl[ni][0] = prmt_lo(e0.x, e0.y);
                bh[ni][1] = prmt_hi(e1.x, e1.y); bl[ni][1] = prmt_lo(e1.x, e1.y);
            }
            #pragma unroll
            for (int mi = 0; mi < 4; ++mi) {
                const uint32_t* ap = As_ + (mi * 16 + g) * 40 + cb;
                uint2 e0 = *(const uint2*)ap;               // row r,   k cb..cb+1
                uint2 e1 = *(const uint2*)(ap + 8*40);      // row r+8, k cb..cb+1
                uint2 e2 = *(const uint2*)(ap + 8);         // row r,   k cb+8..cb+9
                uint2 e3 = *(const uint2*)(ap + 8*40 + 8);  // row r+8, k cb+8..cb+9
                uint32_t ah[4], al[4];
                ah[0] = prmt_hi(e0.x, e0.y); al[0] = prmt_lo(e0.x, e0.y);
                ah[1] = prmt_hi(e1.x, e1.y); al[1] = prmt_lo(e1.x, e1.y);
                ah[2] = prmt_hi(e2.x, e2.y); al[2] = prmt_lo(e2.x, e2.y);
                ah[3] = prmt_hi(e3.x, e3.y); al[3] = prmt_lo(e3.x, e3.y);
                #pragma unroll
                for (int ni = 0; ni < 4; ++ni) {
                    MMA_BF16(acc[mi][ni], ah, bh[ni]);
                    MMA_BF16(acc[mi][ni], ah, bl[ni]);
                    MMA_BF16(acc[mi][ni], al, bh[ni]);
                }
            }
        }
        __syncthreads();
    }

    if (!FUSE) {
        #pragma unroll
        for (int mi = 0; mi < 4; ++mi) {
            const int r = by * 128 + warp_m * 64 + mi * 16 + g;
            #pragma unroll
            for (int ni = 0; ni < 4; ++ni) {
                const int c = bx * 128 + warp_n * 32 + ni * 8 + q4 * 2;
                float e0 = acc[mi][ni][0], e1 = acc[mi][ni][1];
                float e2 = acc[mi][ni][2], e3 = acc[mi][ni][3];
                if (ROUND) { e0 = rna_tf32(e0); e1 = rna_tf32(e1); e2 = rna_tf32(e2); e3 = rna_tf32(e3); }
                *(float2*)&C[(size_t)r * N + c]       = make_float2(e0, e1);
                *(float2*)&C[(size_t)(r + 8) * N + c] = make_float2(e2, e3);
            }
        }
    } else {
        float* Cs = smf;   // 128*129 floats, stages dead now
        #pragma unroll
        for (int mi = 0; mi < 4; ++mi) {
            const int r = warp_m * 64 + mi * 16 + g;
            #pragma unroll
            for (int ni = 0; ni < 4; ++ni) {
                const int c = warp_n * 32 + ni * 8 + q4 * 2;
                Cs[r * 129 + c]           = acc[mi][ni][0];
                Cs[r * 129 + c + 1]       = acc[mi][ni][1];
                Cs[(r + 8) * 129 + c]     = acc[mi][ni][2];
                Cs[(r + 8) * 129 + c + 1] = acc[mi][ni][3];
            }
        }
        __syncthreads();
        if (tid < 128) {
            const int row = by * 128 + tid;
            const float* cr = Cs + tid * 129;
            float ss = 0.f;
            #pragma unroll 16
            for (int j = 0; j < 128; ++j) ss += cr[j] * cr[j];
            const float sc = rsqrtf(ss * (1.0f/128.0f) + 1.1920928955078125e-07f);
            const float* rp = rope + (row & (T_ - 1)) * 128;
            float* op = C + (size_t)row * N + bx * 128;
            #pragma unroll
            for (int f4 = 0; f4 < 64; f4 += 4) {
                float4 o1, o2;
                #pragma unroll
                for (int e = 0; e < 4; ++e) {
                    const int f = f4 + e;
                    const float v1 = cr[f] * sc;
                    const float v2 = cr[f + 64] * sc;
                    const float cz = rp[2*f], sz = rp[2*f + 1];
                    float r1 =  v1 * cz + v2 * sz;
                    float r2 = -v1 * sz + v2 * cz;
                    if (ROUND) { r1 = rna_tf32(r1); r2 = rna_tf32(r2); }
                    (&o1.x)[e] = r1;
                    (&o2.x)[e] = r2;
                }
                *(float4*)(op + f4)      = o1;
                *(float4*)(op + f4 + 64) = o2;
            }
        }
        __syncthreads();
    }
}

// ---------------------------------------------------------------------------
// Tensor-core flash attention (tf32 mma.sync), causal, GQA (round 4, passing).
// Epilogue change: output packed bf16 hi|lo u32 to feed the split-bf16 Wo GEMM.
// ---------------------------------------------------------------------------
#define FKV 8704   // floats per K/V buffer (64*136)

__global__ __launch_bounds__(256, 1)
void flash_tc(const float* __restrict__ Q, const float* __restrict__ K,
              const float* __restrict__ V, uint32_t* __restrict__ Out)
{
    extern __shared__ float sm[];
    float* Psm = sm;                       // 128 x 68
    float* Ks0 = sm + FKV;                 // 64 x 136
    float* Ks1 = sm + 2*FKV;
    float* Vs0 = sm + 3*FKV;
    float* Vs1 = sm + 4*FKV;
    const uint32_t sb = smem_u32(sm);

    const int qt  = (int)gridDim.x - 1 - (int)blockIdx.x;
    const int h   = blockIdx.y;
    const int b   = blockIdx.z;
    const int kvh = h >> 2;
    const int tid = threadIdx.x;
    const int lane = tid & 31;
    const int wm   = tid >> 5;
    const int g    = lane >> 2;
    const int q4   = lane & 3;

    const float scale = 0.08838834764831843f;

    {   // stage Q tile (128 x 128) into K0+K1 region, stride 136
        const float* qp = Q + (size_t)(b*T_ + qt*128) * NQ_ + h*128;
        uint32_t qdst = sb + FKV*4;
        #pragma unroll
        for (int it = 0; it < 16; ++it) {
            int idx = it * 256 + tid;
            int row = idx >> 5, seg = idx & 31;
            CP_ASYNC16(qdst + ((uint32_t)row*136 + seg*4)*4, qp + (size_t)row*NQ_ + seg*4);
        }
        CP_COMMIT();
        CP_WAIT(0);
        __syncthreads();
    }

    uint32_t qf[16][4];
    {
        const float* qs = Ks0 + (wm*16 + g)*136 + 2*q4;
        #pragma unroll
        for (int ks = 0; ks < 16; ++ks) {
            float2 t0 = *(const float2*)(qs + ks*8);
            float2 t1 = *(const float2*)(qs + ks*8 + 8*136);
            qf[ks][0] = rna_tf32_u(t0.x * scale);
            qf[ks][2] = rna_tf32_u(t0.y * scale);
            qf[ks][1] = rna_tf32_u(t1.x * scale);
            qf[ks][3] = rna_tf32_u(t1.y * scale);
        }
    }
    __syncthreads();

    const int njt = 2*qt + 2;

    auto load_k = [&](int jt) {
        uint32_t kd = sb + (uint32_t)((jt & 1) ? 2*FKV : FKV) * 4;
        const float* kp = K + (size_t)(b*T_ + jt*64) * NKV_ + kvh*128;
        #pragma unroll
        for (int it = 0; it < 8; ++it) {
            int idx = it * 256 + tid;
            int row = idx >> 5, seg = idx & 31;
            CP_ASYNC16(kd + ((uint32_t)row*136 + seg*4)*4, kp + (size_t)row*NKV_ + seg*4);
        }
    };
    auto load_v = [&](int jt) {
        uint32_t vd = sb + (uint32_t)((jt & 1) ? 4*FKV : 3*FKV) * 4;
        const float* vp = V + (size_t)(b*T_ + jt*64) * NKV_ + kvh*128;
        #pragma unroll
        for (int it = 0; it < 8; ++it) {
            int idx = it * 256 + tid;
            int row = idx >> 5, seg = idx & 31;
            CP_ASYNC16(vd + ((uint32_t)row*136 + seg*4)*4, vp + (size_t)row*NKV_ + seg*4);
        }
    };

    load_k(0); load_v(0); CP_COMMIT();
    load_k(1); load_v(1); CP_COMMIT();

    float m0 = -1e30f, m1 = -1e30f, l0 = 0.f, l1 = 0.f;
    float O[16][4];
    #pragma unroll
    for (int nf = 0; nf < 16; ++nf)
        #pragma unroll
        for (int e = 0; e < 4; ++e) O[nf][e] = 0.f;

    const int row_g0 = qt*128 + wm*16 + g;
    float* Prow = Psm + (wm*16 + g)*68;

    for (int jt = 0; jt < njt; ++jt) {
        const int cur = jt & 1;
        if (jt == 0) { CP_WAIT(1); } else { CP_WAIT(2); }
        __syncthreads();

        const float* Kc = cur ? Ks1 : Ks0;
        const float* Vc = cur ? Vs1 : Vs0;

        float S[8][4];
        #pragma unroll
        for (int nf = 0; nf < 8; ++nf)
            #pragma unroll
            for (int e = 0; e < 4; ++e) S[nf][e] = 0.f;

        #pragma unroll
        for (int ks = 0; ks < 16; ++ks) {
            const float* kb = Kc + g*136 + ks*8 + 2*q4;
            #pragma unroll
            for (int nf = 0; nf < 8; ++nf) {
                float2 t = *(const float2*)(kb + nf*8*136);
                uint32_t bb[2] = { __float_as_uint(t.x), __float_as_uint(t.y) };
                MMA_TF32(S[nf], qf[ks], bb);
            }
        }

        if (jt >= 2*qt) {
            const int colb = jt*64 + 2*q4;
            #pragma unroll
            for (int nf = 0; nf < 8; ++nf) {
                const int c0 = colb + nf*8;
                if (c0     > row_g0)     S[nf][0] = -1e30f;
                if (c0 + 1 > row_g0)     S[nf][1] = -1e30f;
                if (c0     > row_g0 + 8) S[nf][2] = -1e30f;
                if (c0 + 1 > row_g0 + 8) S[nf][3] = -1e30f;
            }
        }

        float rm0 = -1e30f, rm1 = -1e30f;
        #pragma unroll
        for (int nf = 0; nf < 8; ++nf) {
            rm0 = fmaxf(rm0, fmaxf(S[nf][0], S[nf][1]));
            rm1 = fmaxf(rm1, fmaxf(S[nf][2], S[nf][3]));
        }
        rm0 = fmaxf(rm0, __shfl_xor_sync(0xffffffffu, rm0, 1));
        rm0 = fmaxf(rm0, __shfl_xor_sync(0xffffffffu, rm0, 2));
        rm1 = fmaxf(rm1, __shfl_xor_sync(0xffffffffu, rm1, 1));
        rm1 = fmaxf(rm1, __shfl_xor_sync(0xffffffffu, rm1, 2));

        const float mn0 = fmaxf(m0, rm0), mn1 = fmaxf(m1, rm1);
        const float corr0 = __expf(m0 - mn0), corr1 = __expf(m1 - mn1);
        m0 = mn0; m1 = mn1;

        float rs0 = 0.f, rs1 = 0.f;
        #pragma unroll
        for (int nf = 0; nf < 8; ++nf) {
            S[nf][0] = __expf(S[nf][0] - mn0);
            S[nf][1] = __expf(S[nf][1] - mn0);
            S[nf][2] = __expf(S[nf][2] - mn1);
            S[nf][3] = __expf(S[nf][3] - mn1);
            rs0 += S[nf][0] + S[nf][1];
            rs1 += S[nf][2] + S[nf][3];
        }
        rs0 += __shfl_xor_sync(0xffffffffu, rs0, 1);
        rs0 += __shfl_xor_sync(0xffffffffu, rs0, 2);
        rs1 += __shfl_xor_sync(0xffffffffu, rs1, 1);
        rs1 += __shfl_xor_sync(0xffffffffu, rs1, 2);
        l0 = l0*corr0 + rs0;
        l1 = l1*corr1 + rs1;

        #pragma unroll
        for (int nf = 0; nf < 16; ++nf) {
            O[nf][0] *= corr0; O[nf][1] *= corr0;
            O[nf][2] *= corr1; O[nf][3] *= corr1;
        }

        #pragma unroll
        for (int nf = 0; nf < 8; ++nf) {
            const int c = nf*8 + 2*q4;
            *(float2*)(Prow + c)        = make_float2(rna_tf32(S[nf][0]), rna_tf32(S[nf][1]));
            *(float2*)(Prow + 8*68 + c) = make_float2(rna_tf32(S[nf][2]), rna_tf32(S[nf][3]));
        }
        __syncthreads();

        if (jt + 2 < njt) load_k(jt + 2);
        CP_COMMIT();

        #pragma unroll
        for (int ks = 0; ks < 8; ++ks) {
            uint32_t a[4];
            a[0] = __float_as_uint(Prow[ks*8 + q4]);
            a[2] = __float_as_uint(Prow[ks*8 + q4 + 4]);
            a[1] = __float_as_uint(Prow[8*68 + ks*8 + q4]);
            a[3] = __float_as_uint(Prow[8*68 + ks*8 + q4 + 4]);
            const float* vb = Vc + (ks*8 + q4)*136 + g;
            #pragma unroll
            for (int nf = 0; nf < 16; ++nf) {
                uint32_t bb[2] = { __float_as_uint(vb[nf*8]),
                                   __float_as_uint(vb[nf*8 + 4*136]) };
                MMA_TF32(O[nf], a, bb);
            }
        }
        __syncthreads();

        if (jt + 2 < njt) load_v(jt + 2);
        CP_COMMIT();
    }

    // ---- epilogue: normalize, pack bf16 hi|lo for the split-bf16 Wo GEMM ----
    const float inv0 = 1.0f / l0;
    const float inv1 = 1.0f / l1;
    uint32_t* o0 = Out + (size_t)(b*T_ + row_g0)     * NQ_ + h*128 + 2*q4;
    uint32_t* o1 = Out + (size_t)(b*T_ + row_g0 + 8) * NQ_ + h*128 + 2*q4;
    #pragma unroll
    for (int nf = 0; nf < 16; ++nf) {
        *(uint2*)(o0 + nf*8) = make_uint2(pack_split(O[nf][0]*inv0), pack_split(O[nf][1]*inv0));
        *(uint2*)(o1 + nf*8) = make_uint2(pack_split(O[nf][2]*inv1), pack_split(O[nf][3]*inv1));
    }
}

// ---------------------------------------------------------------------------
__global__ void zero_tail_kernel(float* __restrict__ out, long start, long total) {
    long idx = start + blockIdx.x * (long)blockDim.x + threadIdx.x;
    if (idx < total) out[idx] = 0.f;
}

// ---------------------------------------------------------------------------
extern "C" void kernel_launch(void* const* d_in, const int* in_sizes, int n_in,
                              void* d_out, int out_size) {
    const float* x  = (const float*)d_in[0];
    const float* Wq = (const float*)d_in[1];
    const float* Wk = (const float*)d_in[2];
    const float* Wv = (const float*)d_in[3];
    const float* Wo = (const float*)d_in[4];
    float* out = (float*)d_out;

    float *q, *k, *v, *att, *xr, *wq, *wk, *wv, *wo, *rope;
    cudaGetSymbolAddress((void**)&q,    g_q);
    cudaGetSymbolAddress((void**)&k,    g_k);
    cudaGetSymbolAddress((void**)&v,    g_v);
    cudaGetSymbolAddress((void**)&att,  g_att);
    cudaGetSymbolAddress((void**)&xr,   g_xr);
    cudaGetSymbolAddress((void**)&wq,   g_wq);
    cudaGetSymbolAddress((void**)&wk,   g_wk);
    cudaGetSymbolAddress((void**)&wv,   g_wv);
    cudaGetSymbolAddress((void**)&wo,   g_wo);
    cudaGetSymbolAddress((void**)&rope, g_rope);

    rope_table_kernel<<<(T_*64 + 255)/256, 256>>>(rope);

    // Split-pack operands to bf16 hi|lo (error-free 3-MMA scheme inputs)
    split_bf16_kernel<<<(M_*(long)DM_/4 + 255)/256, 256>>>(x,  (uint32_t*)xr, M_*(long)DM_/4);
    split_bf16_kernel<<<(NQ_*(long)DM_/4 + 255)/256, 256>>>(Wq, (uint32_t*)wq, NQ_*(long)DM_/4);
    split_bf16_kernel<<<(NKV_*(long)DM_/4+ 255)/256, 256>>>(Wk, (uint32_t*)wk, NKV_*(long)DM_/4);
    split_bf16_kernel<<<(NKV_*(long)DM_/4+ 255)/256, 256>>>(Wv, (uint32_t*)wv, NKV_*(long)DM_/4);
    split_bf16_kernel<<<(DM_*(long)NQ_/4 + 255)/256, 256>>>(Wo, (uint32_t*)wo, DM_*(long)NQ_/4);

    const int gsm = 2 * STAGE_B;   // 81920 B -> two CTAs fit per SM
    cudaFuncSetAttribute((tc_gemm<true , false>), cudaFuncAttributeMaxDynamicSharedMemorySize, gsm);
    cudaFuncSetAttribute((tc_gemm<true , true >), cudaFuncAttributeMaxDynamicSharedMemorySize, gsm);
    cudaFuncSetAttribute((tc_gemm<false, true >), cudaFuncAttributeMaxDynamicSharedMemorySize, gsm);
    cudaFuncSetAttribute((tc_gemm<false, false>), cudaFuncAttributeMaxDynamicSharedMemorySize, gsm);

    dim3 blk(256);
    // q: fp32 out (flash scales+rounds it); k,v: tf32-rounded fp32 for flash
    tc_gemm<true , false><<<dim3(NQ_ /128, M_/128), blk, gsm>>>((const uint32_t*)xr, (const uint32_t*)wq, q, M_, NQ_,  DM_, rope);
    tc_gemm<true , true ><<<dim3(NKV_/128, M_/128), blk, gsm>>>((const uint32_t*)xr, (const uint32_t*)wk, k, M_, NKV_, DM_, rope);
    tc_gemm<false, true ><<<dim3(NKV_/128, M_/128), blk, gsm>>>((const uint32_t*)xr, (const uint32_t*)wv, v, M_, NKV_, DM_, nullptr);

    const int fsm = 5 * FKV * 4;   // 174080 B
    cudaFuncSetAttribute(flash_tc, cudaFuncAttributeMaxDynamicSharedMemorySize, fsm);
    flash_tc<<<dim3(T_/128, H_, B_), dim3(256), fsm>>>(q, k, v, (uint32_t*)att);

    tc_gemm<false, false><<<dim3(NQ_/128, M_/128), blk, gsm>>>((const uint32_t*)att, (const uint32_t*)wo, out, M_, NQ_, DM_, nullptr);

    long main_elems = (long)M_ * NQ_;
    long tail = (long)out_size - main_elems;
    if (tail > 0) {
        int nb = (int)((tail + 255) / 256);
        zero_tail_kernel<<<nb, 256>>>(out, main_elems, (long)out_size);
    }
}

// round 8
// speedup vs baseline: 1.2113x; 1.2113x over previous
#include <cuda_runtime.h>
#include <math.h>
#include <stdint.h>

// Problem constants
#define B_    4
#define T_    2048
#define DM_   2048
#define H_    16
#define HKV_  4
#define D_    128
#define M_    (B_*T_)      // 8192 tokens
#define NQ_   (H_*D_)      // 2048
#define NKV_  (HKV_*D_)    // 512

// Scratch (device globals: allocation-free per harness rules)
__device__ float g_q  [M_*NQ_];
__device__ float g_k  [M_*NKV_];
__device__ float g_v  [M_*NKV_];
__device__ float g_att[M_*NQ_];
__device__ float g_xr [M_*DM_];
__device__ float g_wq [NQ_*DM_];
__device__ float g_wk [NKV_*DM_];
__device__ float g_wv [NKV_*DM_];
__device__ float g_wo [DM_*NQ_];
__device__ float g_rope[T_*64*2];

// ---------------------------------------------------------------------------
// Helpers
// ---------------------------------------------------------------------------
__device__ __forceinline__ uint32_t smem_u32(const void* p) {
    uint32_t a;
    asm("{ .reg .u64 t; cvta.to.shared.u64 t, %1; cvt.u32.u64 %0, t; }" : "=r"(a) : "l"(p));
    return a;
}
__device__ __forceinline__ float rna_tf32(float v) {
    uint32_t b;
    asm("cvt.rna.tf32.f32 %0, %1;" : "=r"(b) : "f"(v));
    return __uint_as_float(b);
}
__device__ __forceinline__ uint32_t rna_tf32_u(float v) {
    uint32_t b;
    asm("cvt.rna.tf32.f32 %0, %1;" : "=r"(b) : "f"(v));
    return b;
}

#define CP_ASYNC16(dst, src) \
    asm volatile("cp.async.cg.shared.global [%0], [%1], 16;" :: "r"(dst), "l"(src) : "memory")
#define CP_COMMIT()  asm volatile("cp.async.commit_group;" ::: "memory")
#define CP_WAIT(n)   asm volatile("cp.async.wait_group %0;" :: "n"(n) : "memory")

// mma.sync m16n8k8 tf32 (family-portable)
#define MMA_TF32(c, a, b) \
    asm volatile("mma.sync.aligned.m16n8k8.row.col.f32.tf32.tf32.f32 " \
        "{%0,%1,%2,%3}, {%4,%5,%6,%7}, {%8,%9}, {%0,%1,%2,%3};" \
        : "+f"((c)[0]), "+f"((c)[1]), "+f"((c)[2]), "+f"((c)[3]) \
        : "r"((a)[0]), "r"((a)[1]), "r"((a)[2]), "r"((a)[3]), \
          "r"((b)[0]), "r"((b)[1]))

// ---------------------------------------------------------------------------
// Fused prepass: RNA-round x, Wq, Wk, Wv, Wo to tf32 in ONE launch.
// (Also aligns launch ordering so ncu's -s 5 window profiles flash_tc.)
// ---------------------------------------------------------------------------
__global__ void round5_kernel(const float* __restrict__ x,  const float* __restrict__ wq,
                              const float* __restrict__ wk, const float* __restrict__ wv,
                              const float* __restrict__ wo,
                              float* __restrict__ oxr, float* __restrict__ owq,
                              float* __restrict__ owk, float* __restrict__ owv,
                              float* __restrict__ owo)
{
    const long n_x  = (long)M_  * DM_ / 4;
    const long n_q  = (long)NQ_ * DM_ / 4;
    const long n_kv = (long)NKV_* DM_ / 4;
    long j = blockIdx.x * (long)blockDim.x + threadIdx.x;
    const float* src; float* dst;
    if (j < n_x)                { src = x;  dst = oxr; }
    else if ((j -= n_x) < n_q)  { src = wq; dst = owq; }
    else if ((j -= n_q) < n_kv) { src = wk; dst = owk; }
    else if ((j -= n_kv) < n_kv){ src = wv; dst = owv; }
    else if ((j -= n_kv) < n_q) { src = wo; dst = owo; }
    else return;
    float4 v = ((const float4*)src)[j];
    v.x = rna_tf32(v.x); v.y = rna_tf32(v.y); v.z = rna_tf32(v.z); v.w = rna_tf32(v.w);
    ((float4*)dst)[j] = v;
}

__global__ void rope_table_kernel(float* __restrict__ tab) {
    int idx = blockIdx.x * blockDim.x + threadIdx.x;
    if (idx >= T_ * 64) return;
    int t = idx >> 6, f = idx & 63;
    double invf = exp(-((double)f / 64.0) * log(10000.0));
    float ang = (float)t * (float)invf;
    tab[idx*2 + 0] = (float)cos((double)ang);
    tab[idx*2 + 1] = (float)sin((double)ang);
}

// ---------------------------------------------------------------------------
// HMMA tf32 GEMM: C[M,N] = A[M,K] @ W[N,K]^T  (R6 configuration — proven)
// CTA 128x128x32, 8 warps (2m x 4n, 64x32 warp tiles), 2 CTAs/SM via
// __launch_bounds__(256,2). Double-buffered cp.async; stride-40 rows;
// permuted-k conflict-free fragment loads.
// FUSE: per-head RMSNorm + rotary through a smem C-stage.
// ---------------------------------------------------------------------------
#define STAGE_F 10240
#define STAGE_B (STAGE_F*4)

template<bool FUSE, bool ROUND>
__global__ __launch_bounds__(256, 2)
void tc_gemm(const float* __restrict__ A, const float* __restrict__ W,
             float* __restrict__ C, int M, int N, int K,
             const float* __restrict__ rope)
{
    extern __shared__ float smf[];
    const uint32_t sbase = smem_u32(smf);

    const int tid  = threadIdx.x;
    const int lane = tid & 31;
    const int wid  = tid >> 5;
    const int warp_m = wid >> 2;
    const int warp_n = wid & 3;
    const int bx = blockIdx.x, by = blockIdx.y;

    const float* Ab = A + (size_t)(by * 128) * K;
    const float* Wb = W + (size_t)(bx * 128) * K;

    float acc[4][4][4];
    #pragma unroll
    for (int mi = 0; mi < 4; ++mi)
        #pragma unroll
        for (int ni = 0; ni < 4; ++ni)
            #pragma unroll
            for (int e = 0; e < 4; ++e) acc[mi][ni][e] = 0.f;

    const int KT = K >> 5;

    auto load_stage = [&](int s, int kt) {
        uint32_t aS = sbase + s * STAGE_B;
        uint32_t bS = aS + 20480;
        const float* ap = Ab + kt * 32;
        const float* wp = Wb + kt * 32;
        #pragma unroll
        for (int it = 0; it < 4; ++it) {
            int idx = it * 256 + tid;
            int row = idx >> 3, seg = idx & 7;
            uint32_t so = (uint32_t)row * 160 + (uint32_t)seg * 16;
            CP_ASYNC16(aS + so, ap + (size_t)row * K + seg * 4);
            CP_ASYNC16(bS + so, wp + (size_t)row * K + seg * 4);
        }
    };

    load_stage(0, 0);
    CP_COMMIT();

    for (int kt = 0; kt < KT; ++kt) {
        const int cur = kt & 1;
        if (kt + 1 < KT) {
            load_stage(cur ^ 1, kt + 1);
            CP_COMMIT();
            CP_WAIT(1);
        } else {
            CP_WAIT(0);
        }
        __syncthreads();

        const float* As_ = smf + cur * STAGE_F + warp_m * (64 * 40);
        const float* Bs_ = smf + cur * STAGE_F + 5120 + warp_n * (32 * 40);

        #pragma unroll
        for (int ks = 0; ks < 4; ++ks) {
            const int col = ks * 8 + 2 * (lane & 3);
            uint32_t a[4][4], b[4][2];
            #pragma unroll
            for (int ni = 0; ni < 4; ++ni) {
                float2 t = *(const float2*)&Bs_[(ni * 8 + (lane >> 2)) * 40 + col];
                b[ni][0] = __float_as_uint(t.x);
                b[ni][1] = __float_as_uint(t.y);
            }
            #pragma unroll
            for (int mi = 0; mi < 4; ++mi) {
                const int r = mi * 16 + (lane >> 2);
                float2 t0 = *(const float2*)&As_[r * 40 + col];
                float2 t1 = *(const float2*)&As_[(r + 8) * 40 + col];
                a[mi][0] = __float_as_uint(t0.x);
                a[mi][2] = __float_as_uint(t0.y);
                a[mi][1] = __float_as_uint(t1.x);
                a[mi][3] = __float_as_uint(t1.y);
            }
            #pragma unroll
            for (int mi = 0; mi < 4; ++mi)
                #pragma unroll
                for (int ni = 0; ni < 4; ++ni)
                    MMA_TF32(acc[mi][ni], a[mi], b[ni]);
        }
        __syncthreads();
    }

    if (!FUSE) {
        #pragma unroll
        for (int mi = 0; mi < 4; ++mi) {
            const int r = by * 128 + warp_m * 64 + mi * 16 + (lane >> 2);
            #pragma unroll
            for (int ni = 0; ni < 4; ++ni) {
                const int c = bx * 128 + warp_n * 32 + ni * 8 + (lane & 3) * 2;
                float e0 = acc[mi][ni][0], e1 = acc[mi][ni][1];
                float e2 = acc[mi][ni][2], e3 = acc[mi][ni][3];
                if (ROUND) { e0 = rna_tf32(e0); e1 = rna_tf32(e1); e2 = rna_tf32(e2); e3 = rna_tf32(e3); }
                *(float2*)&C[(size_t)r * N + c]       = make_float2(e0, e1);
                *(float2*)&C[(size_t)(r + 8) * N + c] = make_float2(e2, e3);
            }
        }
    } else {
        float* Cs = smf;   // 128*129 floats = 66048 B <= 2*STAGE_B (stages dead)
        #pragma unroll
        for (int mi = 0; mi < 4; ++mi) {
            const int r = warp_m * 64 + mi * 16 + (lane >> 2);
            #pragma unroll
            for (int ni = 0; ni < 4; ++ni) {
                const int c = warp_n * 32 + ni * 8 + (lane & 3) * 2;
                Cs[r * 129 + c]           = acc[mi][ni][0];
                Cs[r * 129 + c + 1]       = acc[mi][ni][1];
                Cs[(r + 8) * 129 + c]     = acc[mi][ni][2];
                Cs[(r + 8) * 129 + c + 1] = acc[mi][ni][3];
            }
        }
        __syncthreads();
        if (tid < 128) {
            const int row = by * 128 + tid;
            const float* cr = Cs + tid * 129;
            float ss = 0.f;
            #pragma unroll 16
            for (int j = 0; j < 128; ++j) ss += cr[j] * cr[j];
            const float sc = rsqrtf(ss * (1.0f/128.0f) + 1.1920928955078125e-07f);
            const float* rp = rope + (row & (T_ - 1)) * 128;
            float* op = C + (size_t)row * N + bx * 128;
            #pragma unroll
            for (int f4 = 0; f4 < 64; f4 += 4) {
                float4 o1, o2;
                #pragma unroll
                for (int e = 0; e < 4; ++e) {
                    const int f = f4 + e;
                    const float v1 = cr[f] * sc;
                    const float v2 = cr[f + 64] * sc;
                    const float cz = rp[2*f], sz = rp[2*f + 1];
                    float r1 =  v1 * cz + v2 * sz;
                    float r2 = -v1 * sz + v2 * cz;
                    if (ROUND) { r1 = rna_tf32(r1); r2 = rna_tf32(r2); }
                    (&o1.x)[e] = r1;
                    (&o2.x)[e] = r2;
                }
                *(float4*)(op + f4)      = o1;
                *(float4*)(op + f4 + 64) = o2;
            }
        }
        __syncthreads();
    }
}

// ---------------------------------------------------------------------------
// Tensor-core flash attention (tf32 mma.sync), causal, GQA. (R4/R6, proven)
// ---------------------------------------------------------------------------
#define FKV 8704   // floats per K/V buffer (64*136)

__global__ __launch_bounds__(256, 1)
void flash_tc(const float* __restrict__ Q, const float* __restrict__ K,
              const float* __restrict__ V, float* __restrict__ Out)
{
    extern __shared__ float sm[];
    float* Psm = sm;                       // 128 x 68
    float* Ks0 = sm + FKV;                 // 64 x 136
    float* Ks1 = sm + 2*FKV;
    float* Vs0 = sm + 3*FKV;
    float* Vs1 = sm + 4*FKV;
    const uint32_t sb = smem_u32(sm);

    const int qt  = (int)gridDim.x - 1 - (int)blockIdx.x;
    const int h   = blockIdx.y;
    const int b   = blockIdx.z;
    const int kvh = h >> 2;
    const int tid = threadIdx.x;
    const int lane = tid & 31;
    const int wm   = tid >> 5;
    const int g    = lane >> 2;
    const int q4   = lane & 3;

    const float scale = 0.08838834764831843f;

    {   // stage Q tile (128 x 128) into K0+K1 region, stride 136
        const float* qp = Q + (size_t)(b*T_ + qt*128) * NQ_ + h*128;
        uint32_t qdst = sb + FKV*4;
        #pragma unroll
        for (int it = 0; it < 16; ++it) {
            int idx = it * 256 + tid;
            int row = idx >> 5, seg = idx & 31;
            CP_ASYNC16(qdst + ((uint32_t)row*136 + seg*4)*4, qp + (size_t)row*NQ_ + seg*4);
        }
        CP_COMMIT();
        CP_WAIT(0);
        __syncthreads();
    }

    uint32_t qf[16][4];
    {
        const float* qs = Ks0 + (wm*16 + g)*136 + 2*q4;
        #pragma unroll
        for (int ks = 0; ks < 16; ++ks) {
            float2 t0 = *(const float2*)(qs + ks*8);
            float2 t1 = *(const float2*)(qs + ks*8 + 8*136);
            qf[ks][0] = rna_tf32_u(t0.x * scale);
            qf[ks][2] = rna_tf32_u(t0.y * scale);
            qf[ks][1] = rna_tf32_u(t1.x * scale);
            qf[ks][3] = rna_tf32_u(t1.y * scale);
        }
    }
    __syncthreads();

    const int njt = 2*qt + 2;

    auto load_k = [&](int jt) {
        uint32_t kd = sb + (uint32_t)((jt & 1) ? 2*FKV : FKV) * 4;
        const float* kp = K + (size_t)(b*T_ + jt*64) * NKV_ + kvh*128;
        #pragma unroll
        for (int it = 0; it < 8; ++it) {
            int idx = it * 256 + tid;
            int row = idx >> 5, seg = idx & 31;
            CP_ASYNC16(kd + ((uint32_t)row*136 + seg*4)*4, kp + (size_t)row*NKV_ + seg*4);
        }
    };
    auto load_v = [&](int jt) {
        uint32_t vd = sb + (uint32_t)((jt & 1) ? 4*FKV : 3*FKV) * 4;
        const float* vp = V + (size_t)(b*T_ + jt*64) * NKV_ + kvh*128;
        #pragma unroll
        for (int it = 0; it < 8; ++it) {
            int idx = it * 256 + tid;
            int row = idx >> 5, seg = idx & 31;
            CP_ASYNC16(vd + ((uint32_t)row*136 + seg*4)*4, vp + (size_t)row*NKV_ + seg*4);
        }
    };

    load_k(0); load_v(0); CP_COMMIT();
    load_k(1); load_v(1); CP_COMMIT();

    float m0 = -1e30f, m1 = -1e30f, l0 = 0.f, l1 = 0.f;
    float O[16][4];
    #pragma unroll
    for (int nf = 0; nf < 16; ++nf)
        #pragma unroll
        for (int e = 0; e < 4; ++e) O[nf][e] = 0.f;

    const int row_g0 = qt*128 + wm*16 + g;
    float* Prow = Psm + (wm*16 + g)*68;

    for (int jt = 0; jt < njt; ++jt) {
        const int cur = jt & 1;
        if (jt == 0) { CP_WAIT(1); } else { CP_WAIT(2); }
        __syncthreads();

        const float* Kc = cur ? Ks1 : Ks0;
        const float* Vc = cur ? Vs1 : Vs0;

        float S[8][4];
        #pragma unroll
        for (int nf = 0; nf < 8; ++nf)
            #pragma unroll
            for (int e = 0; e < 4; ++e) S[nf][e] = 0.f;

        #pragma unroll
        for (int ks = 0; ks < 16; ++ks) {
            const float* kb = Kc + g*136 + ks*8 + 2*q4;
            #pragma unroll
            for (int nf = 0; nf < 8; ++nf) {
                float2 t = *(const float2*)(kb + nf*8*136);
                uint32_t bb[2] = { __float_as_uint(t.x), __float_as_uint(t.y) };
                MMA_TF32(S[nf], qf[ks], bb);
            }
        }

        if (jt >= 2*qt) {
            const int colb = jt*64 + 2*q4;
            #pragma unroll
            for (int nf = 0; nf < 8; ++nf) {
                const int c0 = colb + nf*8;
                if (c0     > row_g0)     S[nf][0] = -1e30f;
                if (c0 + 1 > row_g0)     S[nf][1] = -1e30f;
                if (c0     > row_g0 + 8) S[nf][2] = -1e30f;
                if (c0 + 1 > row_g0 + 8) S[nf][3] = -1e30f;
            }
        }

        float rm0 = -1e30f, rm1 = -1e30f;
        #pragma unroll
        for (int nf = 0; nf < 8; ++nf) {
            rm0 = fmaxf(rm0, fmaxf(S[nf][0], S[nf][1]));
            rm1 = fmaxf(rm1, fmaxf(S[nf][2], S[nf][3]));
        }
        rm0 = fmaxf(rm0, __shfl_xor_sync(0xffffffffu, rm0, 1));
        rm0 = fmaxf(rm0, __shfl_xor_sync(0xffffffffu, rm0, 2));
        rm1 = fmaxf(rm1, __shfl_xor_sync(0xffffffffu, rm1, 1));
        rm1 = fmaxf(rm1, __shfl_xor_sync(0xffffffffu, rm1, 2));

        const float mn0 = fmaxf(m0, rm0), mn1 = fmaxf(m1, rm1);
        const float corr0 = __expf(m0 - mn0), corr1 = __expf(m1 - mn1);
        m0 = mn0; m1 = mn1;

        float rs0 = 0.f, rs1 = 0.f;
        #pragma unroll
        for (int nf = 0; nf < 8; ++nf) {
            S[nf][0] = __expf(S[nf][0] - mn0);
            S[nf][1] = __expf(S[nf][1] - mn0);
            S[nf][2] = __expf(S[nf][2] - mn1);
            S[nf][3] = __expf(S[nf][3] - mn1);
            rs0 += S[nf][0] + S[nf][1];
            rs1 += S[nf][2] + S[nf][3];
        }
        rs0 += __shfl_xor_sync(0xffffffffu, rs0, 1);
        rs0 += __shfl_xor_sync(0xffffffffu, rs0, 2);
        rs1 += __shfl_xor_sync(0xffffffffu, rs1, 1);
        rs1 += __shfl_xor_sync(0xffffffffu, rs1, 2);
        l0 = l0*corr0 + rs0;
        l1 = l1*corr1 + rs1;

        #pragma unroll
        for (int nf = 0; nf < 16; ++nf) {
            O[nf][0] *= corr0; O[nf][1] *= corr0;
            O[nf][2] *= corr1; O[nf][3] *= corr1;
        }

        #pragma unroll
        for (int nf = 0; nf < 8; ++nf) {
            const int c = nf*8 + 2*q4;
            *(float2*)(Prow + c)        = make_float2(rna_tf32(S[nf][0]), rna_tf32(S[nf][1]));
            *(float2*)(Prow + 8*68 + c) = make_float2(rna_tf32(S[nf][2]), rna_tf32(S[nf][3]));
        }
        __syncthreads();

        if (jt + 2 < njt) load_k(jt + 2);
        CP_COMMIT();

        #pragma unroll
        for (int ks = 0; ks < 8; ++ks) {
            uint32_t a[4];
            a[0] = __float_as_uint(Prow[ks*8 + q4]);
            a[2] = __float_as_uint(Prow[ks*8 + q4 + 4]);
            a[1] = __float_as_uint(Prow[8*68 + ks*8 + q4]);
            a[3] = __float_as_uint(Prow[8*68 + ks*8 + q4 + 4]);
            const float* vb = Vc + (ks*8 + q4)*136 + g;
            #pragma unroll
            for (int nf = 0; nf < 16; ++nf) {
                uint32_t bb[2] = { __float_as_uint(vb[nf*8]),
                                   __float_as_uint(vb[nf*8 + 4*136]) };
                MMA_TF32(O[nf], a, bb);
            }
        }
        __syncthreads();

        if (jt + 2 < njt) load_v(jt + 2);
        CP_COMMIT();
    }

    const float inv0 = 1.0f / l0;
    const float inv1 = 1.0f / l1;
    float* o0 = Out + (size_t)(b*T_ + row_g0)     * NQ_ + h*128 + 2*q4;
    float* o1 = Out + (size_t)(b*T_ + row_g0 + 8) * NQ_ + h*128 + 2*q4;
    #pragma unroll
    for (int nf = 0; nf < 16; ++nf) {
        *(float2*)(o0 + nf*8) = make_float2(rna_tf32(O[nf][0]*inv0), rna_tf32(O[nf][1]*inv0));
        *(float2*)(o1 + nf*8) = make_float2(rna_tf32(O[nf][2]*inv1), rna_tf32(O[nf][3]*inv1));
    }
}

// ---------------------------------------------------------------------------
__global__ void zero_tail_kernel(float* __restrict__ out, long start, long total) {
    long idx = start + blockIdx.x * (long)blockDim.x + threadIdx.x;
    if (idx < total) out[idx] = 0.f;
}

// ---------------------------------------------------------------------------
extern "C" void kernel_launch(void* const* d_in, const int* in_sizes, int n_in,
                              void* d_out, int out_size) {
    const float* x  = (const float*)d_in[0];
    const float* Wq = (const float*)d_in[1];
    const float* Wk = (const float*)d_in[2];
    const float* Wv = (const float*)d_in[3];
    const float* Wo = (const float*)d_in[4];
    float* out = (float*)d_out;

    float *q, *k, *v, *att, *xr, *wq, *wk, *wv, *wo, *rope;
    cudaGetSymbolAddress((void**)&q,    g_q);
    cudaGetSymbolAddress((void**)&k,    g_k);
    cudaGetSymbolAddress((void**)&v,    g_v);
    cudaGetSymbolAddress((void**)&att,  g_att);
    cudaGetSymbolAddress((void**)&xr,   g_xr);
    cudaGetSymbolAddress((void**)&wq,   g_wq);
    cudaGetSymbolAddress((void**)&wk,   g_wk);
    cudaGetSymbolAddress((void**)&wv,   g_wv);
    cudaGetSymbolAddress((void**)&wo,   g_wo);
    cudaGetSymbolAddress((void**)&rope, g_rope);

    // Launch order matters for ncu (-s 5 -c 1 profiles launch #6 = flash_tc):
    // 1 rope, 2 round5, 3 q-GEMM, 4 k-GEMM, 5 v-GEMM, 6 flash, 7 Wo, 8 tail.
    rope_table_kernel<<<(T_*64 + 255)/256, 256>>>(rope);

    const long total4 = ((long)M_*DM_ + (long)NQ_*DM_ + 2L*NKV_*DM_ + (long)DM_*NQ_) / 4;
    round5_kernel<<<(int)((total4 + 255) / 256), 256>>>(x, Wq, Wk, Wv, Wo,
                                                        xr, wq, wk, wv, wo);

    const int gsm = 2 * STAGE_B;   // 81920 B -> two CTAs per SM
    cudaFuncSetAttribute((tc_gemm<true , false>), cudaFuncAttributeMaxDynamicSharedMemorySize, gsm);
    cudaFuncSetAttribute((tc_gemm<true , true >), cudaFuncAttributeMaxDynamicSharedMemorySize, gsm);
    cudaFuncSetAttribute((tc_gemm<false, true >), cudaFuncAttributeMaxDynamicSharedMemorySize, gsm);
    cudaFuncSetAttribute((tc_gemm<false, false>), cudaFuncAttributeMaxDynamicSharedMemorySize, gsm);

    dim3 blk(256);
    // q: fp32 out (flash scales+rounds it); k,v: tf32-rounded at write
    tc_gemm<true , false><<<dim3(NQ_ /128, M_/128), blk, gsm>>>(xr, wq, q, M_, NQ_,  DM_, rope);
    tc_gemm<true , true ><<<dim3(NKV_/128, M_/128), blk, gsm>>>(xr, wk, k, M_, NKV_, DM_, rope);
    tc_gemm<false, true ><<<dim3(NKV_/128, M_/128), blk, gsm>>>(xr, wv, v, M_, NKV_, DM_, nullptr);

    const int fsm = 5 * FKV * 4;   // 174080 B
    cudaFuncSetAttribute(flash_tc, cudaFuncAttributeMaxDynamicSharedMemorySize, fsm);
    flash_tc<<<dim3(T_/128, H_, B_), dim3(256), fsm>>>(q, k, v, att);

    tc_gemm<false, false><<<dim3(NQ_/128, M_/128), blk, gsm>>>(att, wo, out, M_, NQ_, DM_, nullptr);

    long main_elems = (long)M_ * NQ_;
    long tail = (long)out_size - main_elems;
    if (tail > 0) {
        int nb = (int)((tail + 255) / 256);
        zero_tail_kernel<<<nb, 256>>>(out, main_elems, (long)out_size);
    }
}

// round 9
// speedup vs baseline: 1.2116x; 1.0003x over previous
#include <cuda_runtime.h>
#include <math.h>
#include <stdint.h>

// Problem constants
#define B_    4
#define T_    2048
#define DM_   2048
#define H_    16
#define HKV_  4
#define D_    128
#define M_    (B_*T_)      // 8192 tokens
#define NQ_   (H_*D_)      // 2048
#define NKV_  (HKV_*D_)    // 512

// Scratch (device globals: allocation-free per harness rules)
__device__ float g_q  [M_*NQ_];
__device__ float g_k  [M_*NKV_];
__device__ float g_v  [M_*NKV_];
__device__ float g_att[M_*NQ_];
__device__ float g_xr [M_*DM_];
__device__ float g_wq [NQ_*DM_];
__device__ float g_wk [NKV_*DM_];
__device__ float g_wv [NKV_*DM_];
__device__ float g_wo [DM_*NQ_];
__device__ float g_rope[T_*64*2];

// ---------------------------------------------------------------------------
// Helpers
// ---------------------------------------------------------------------------
__device__ __forceinline__ uint32_t smem_u32(const void* p) {
    uint32_t a;
    asm("{ .reg .u64 t; cvta.to.shared.u64 t, %1; cvt.u32.u64 %0, t; }" : "=r"(a) : "l"(p));
    return a;
}
__device__ __forceinline__ float rna_tf32(float v) {
    uint32_t b;
    asm("cvt.rna.tf32.f32 %0, %1;" : "=r"(b) : "f"(v));
    return __uint_as_float(b);
}
__device__ __forceinline__ uint32_t rna_tf32_u(float v) {
    uint32_t b;
    asm("cvt.rna.tf32.f32 %0, %1;" : "=r"(b) : "f"(v));
    return b;
}

#define CP_ASYNC16(dst, src) \
    asm volatile("cp.async.cg.shared.global [%0], [%1], 16;" :: "r"(dst), "l"(src) : "memory")
#define CP_COMMIT()  asm volatile("cp.async.commit_group;" ::: "memory")
#define CP_WAIT(n)   asm volatile("cp.async.wait_group %0;" :: "n"(n) : "memory")

// mma.sync m16n8k8 tf32 (family-portable)
#define MMA_TF32(c, a, b) \
    asm volatile("mma.sync.aligned.m16n8k8.row.col.f32.tf32.tf32.f32 " \
        "{%0,%1,%2,%3}, {%4,%5,%6,%7}, {%8,%9}, {%0,%1,%2,%3};" \
        : "+f"((c)[0]), "+f"((c)[1]), "+f"((c)[2]), "+f"((c)[3]) \
        : "r"((a)[0]), "r"((a)[1]), "r"((a)[2]), "r"((a)[3]), \
          "r"((b)[0]), "r"((b)[1]))

// ---------------------------------------------------------------------------
// Fused prepass: RNA-round x, Wq, Wk, Wv, Wo to tf32 in ONE launch.
// ---------------------------------------------------------------------------
__global__ void round5_kernel(const float* __restrict__ x,  const float* __restrict__ wq,
                              const float* __restrict__ wk, const float* __restrict__ wv,
                              const float* __restrict__ wo,
                              float* __restrict__ oxr, float* __restrict__ owq,
                              float* __restrict__ owk, float* __restrict__ owv,
                              float* __restrict__ owo)
{
    const long n_x  = (long)M_  * DM_ / 4;
    const long n_q  = (long)NQ_ * DM_ / 4;
    const long n_kv = (long)NKV_* DM_ / 4;
    long j = blockIdx.x * (long)blockDim.x + threadIdx.x;
    const float* src; float* dst;
    if (j < n_x)                { src = x;  dst = oxr; }
    else if ((j -= n_x) < n_q)  { src = wq; dst = owq; }
    else if ((j -= n_q) < n_kv) { src = wk; dst = owk; }
    else if ((j -= n_kv) < n_kv){ src = wv; dst = owv; }
    else if ((j -= n_kv) < n_q) { src = wo; dst = owo; }
    else return;
    float4 v = ((const float4*)src)[j];
    v.x = rna_tf32(v.x); v.y = rna_tf32(v.y); v.z = rna_tf32(v.z); v.w = rna_tf32(v.w);
    ((float4*)dst)[j] = v;
}

__global__ void rope_table_kernel(float* __restrict__ tab) {
    int idx = blockIdx.x * blockDim.x + threadIdx.x;
    if (idx >= T_ * 64) return;
    int t = idx >> 6, f = idx & 63;
    double invf = exp(-((double)f / 64.0) * log(10000.0));
    float ang = (float)t * (float)invf;
    tab[idx*2 + 0] = (float)cos((double)ang);
    tab[idx*2 + 1] = (float)sin((double)ang);
}

// ---------------------------------------------------------------------------
// HMMA tf32 GEMM: C[M,N] = A[M,K] @ W[N,K]^T  (NT, K-major, tf32-rounded in)
// NEW SHAPE: CTA 128x128x32 with FOUR warps (128 threads), 2m x 2n grid of
// 64x64 warp tiles. __launch_bounds__(128, 2) -> 2 CTAs/SM, 256-reg budget:
// acc 128 + double-buffered fragments (64) fit with no spill. Two co-resident
// CTAs cover each other's barrier/CP_WAIT stalls (R5's monolithic-CTA flaw).
// Fragments for ks+1 are explicitly prefetched during the 32 MMAs of ks.
// Stage layout identical to R6 (stride-40 rows, permuted-k conflict-free).
// FUSE: per-head RMSNorm + rotary through a smem C-stage.
// ---------------------------------------------------------------------------
#define STAGE_F 10240
#define STAGE_B (STAGE_F*4)

template<bool FUSE, bool ROUND>
__global__ __launch_bounds__(128, 2)
void tc_gemm(const float* __restrict__ A, const float* __restrict__ W,
             float* __restrict__ C, int M, int N, int K,
             const float* __restrict__ rope)
{
    extern __shared__ float smf[];
    const uint32_t sbase = smem_u32(smf);

    const int tid  = threadIdx.x;
    const int lane = tid & 31;
    const int wid  = tid >> 5;          // 0..3
    const int warp_m = wid >> 1;        // 0..1 (64-row block)
    const int warp_n = wid & 1;         // 0..1 (64-col block)
    const int g  = lane >> 2;           // 0..7
    const int q4 = lane & 3;            // 0..3
    const int bx = blockIdx.x, by = blockIdx.y;

    const float* Ab = A + (size_t)(by * 128) * K;
    const float* Wb = W + (size_t)(bx * 128) * K;

    float acc[4][8][4];
    #pragma unroll
    for (int mi = 0; mi < 4; ++mi)
        #pragma unroll
        for (int ni = 0; ni < 8; ++ni)
            #pragma unroll
            for (int e = 0; e < 4; ++e) acc[mi][ni][e] = 0.f;

    const int KT = K >> 5;

    auto load_stage = [&](int s, int kt) {
        uint32_t aS = sbase + s * STAGE_B;
        uint32_t bS = aS + 20480;
        const float* ap = Ab + kt * 32;
        const float* wp = Wb + kt * 32;
        #pragma unroll
        for (int it = 0; it < 8; ++it) {
            int idx = it * 128 + tid;
            int row = idx >> 3, seg = idx & 7;
            uint32_t so = (uint32_t)row * 160 + (uint32_t)seg * 16;
            CP_ASYNC16(aS + so, ap + (size_t)row * K + seg * 4);
            CP_ASYNC16(bS + so, wp + (size_t)row * K + seg * 4);
        }
    };

    load_stage(0, 0);
    CP_COMMIT();

    for (int kt = 0; kt < KT; ++kt) {
        const int cur = kt & 1;
        if (kt + 1 < KT) {
            load_stage(cur ^ 1, kt + 1);
            CP_COMMIT();
            CP_WAIT(1);
        } else {
            CP_WAIT(0);
        }
        __syncthreads();

        const float* As_ = smf + cur * STAGE_F + warp_m * (64 * 40);
        const float* Bs_ = smf + cur * STAGE_F + 5120 + warp_n * (64 * 40);

        // Fragment registers, double-buffered across ks steps.
        uint32_t aF[2][16], bF[2][16];

        auto load_frags = [&](int ks, uint32_t* a, uint32_t* b) {
            const int col = ks * 8 + 2 * q4;
            #pragma unroll
            for (int ni = 0; ni < 8; ++ni) {
                float2 t = *(const float2*)&Bs_[(ni * 8 + g) * 40 + col];
                b[ni*2]   = __float_as_uint(t.x);
                b[ni*2+1] = __float_as_uint(t.y);
            }
            #pragma unroll
            for (int mi = 0; mi < 4; ++mi) {
                float2 t0 = *(const float2*)&As_[(mi * 16 + g) * 40 + col];
                float2 t1 = *(const float2*)&As_[(mi * 16 + g + 8) * 40 + col];
                a[mi*4+0] = __float_as_uint(t0.x);
                a[mi*4+2] = __float_as_uint(t0.y);
                a[mi*4+1] = __float_as_uint(t1.x);
                a[mi*4+3] = __float_as_uint(t1.y);
            }
        };

        load_frags(0, aF[0], bF[0]);
        #pragma unroll
        for (int ks = 0; ks < 4; ++ks) {
            const int cb = ks & 1;
            if (ks < 3) load_frags(ks + 1, aF[cb ^ 1], bF[cb ^ 1]);
            #pragma unroll
            for (int mi = 0; mi < 4; ++mi)
                #pragma unroll
                for (int ni = 0; ni < 8; ++ni)
                    MMA_TF32(acc[mi][ni], &aF[cb][mi*4], &bF[cb][ni*2]);
        }
        __syncthreads();
    }

    if (!FUSE) {
        #pragma unroll
        for (int mi = 0; mi < 4; ++mi) {
            const int r = by * 128 + warp_m * 64 + mi * 16 + g;
            #pragma unroll
            for (int ni = 0; ni < 8; ++ni) {
                const int c = bx * 128 + warp_n * 64 + ni * 8 + q4 * 2;
                float e0 = acc[mi][ni][0], e1 = acc[mi][ni][1];
                float e2 = acc[mi][ni][2], e3 = acc[mi][ni][3];
                if (ROUND) { e0 = rna_tf32(e0); e1 = rna_tf32(e1); e2 = rna_tf32(e2); e3 = rna_tf32(e3); }
                *(float2*)&C[(size_t)r * N + c]       = make_float2(e0, e1);
                *(float2*)&C[(size_t)(r + 8) * N + c] = make_float2(e2, e3);
            }
        }
    } else {
        float* Cs = smf;   // 128*129 floats = 66048 B <= 2*STAGE_B (stages dead)
        #pragma unroll
        for (int mi = 0; mi < 4; ++mi) {
            const int r = warp_m * 64 + mi * 16 + g;
            #pragma unroll
            for (int ni = 0; ni < 8; ++ni) {
                const int c = warp_n * 64 + ni * 8 + q4 * 2;
                Cs[r * 129 + c]           = acc[mi][ni][0];
                Cs[r * 129 + c + 1]       = acc[mi][ni][1];
                Cs[(r + 8) * 129 + c]     = acc[mi][ni][2];
                Cs[(r + 8) * 129 + c + 1] = acc[mi][ni][3];
            }
        }
        __syncthreads();
        {
            const int row = by * 128 + tid;      // 128 threads = 128 rows
            const float* cr = Cs + tid * 129;
            float ss = 0.f;
            #pragma unroll 16
            for (int j = 0; j < 128; ++j) ss += cr[j] * cr[j];
            const float sc = rsqrtf(ss * (1.0f/128.0f) + 1.1920928955078125e-07f);
            const float* rp = rope + (row & (T_ - 1)) * 128;
            float* op = C + (size_t)row * N + bx * 128;
            #pragma unroll
            for (int f4 = 0; f4 < 64; f4 += 4) {
                float4 o1, o2;
                #pragma unroll
                for (int e = 0; e < 4; ++e) {
                    const int f = f4 + e;
                    const float v1 = cr[f] * sc;
                    const float v2 = cr[f + 64] * sc;
                    const float cz = rp[2*f], sz = rp[2*f + 1];
                    float r1 =  v1 * cz + v2 * sz;
                    float r2 = -v1 * sz + v2 * cz;
                    if (ROUND) { r1 = rna_tf32(r1); r2 = rna_tf32(r2); }
                    (&o1.x)[e] = r1;
                    (&o2.x)[e] = r2;
                }
                *(float4*)(op + f4)      = o1;
                *(float4*)(op + f4 + 64) = o2;
            }
        }
        __syncthreads();
    }
}

// ---------------------------------------------------------------------------
// Tensor-core flash attention (tf32 mma.sync), causal, GQA. (R4/R6, proven)
// ---------------------------------------------------------------------------
#define FKV 8704   // floats per K/V buffer (64*136)

__global__ __launch_bounds__(256, 1)
void flash_tc(const float* __restrict__ Q, const float* __restrict__ K,
              const float* __restrict__ V, float* __restrict__ Out)
{
    extern __shared__ float sm[];
    float* Psm = sm;                       // 128 x 68
    float* Ks0 = sm + FKV;                 // 64 x 136
    float* Ks1 = sm + 2*FKV;
    float* Vs0 = sm + 3*FKV;
    float* Vs1 = sm + 4*FKV;
    const uint32_t sb = smem_u32(sm);

    const int qt  = (int)gridDim.x - 1 - (int)blockIdx.x;
    const int h   = blockIdx.y;
    const int b   = blockIdx.z;
    const int kvh = h >> 2;
    const int tid = threadIdx.x;
    const int lane = tid & 31;
    const int wm   = tid >> 5;
    const int g    = lane >> 2;
    const int q4   = lane & 3;

    const float scale = 0.08838834764831843f;

    {   // stage Q tile (128 x 128) into K0+K1 region, stride 136
        const float* qp = Q + (size_t)(b*T_ + qt*128) * NQ_ + h*128;
        uint32_t qdst = sb + FKV*4;
        #pragma unroll
        for (int it = 0; it < 16; ++it) {
            int idx = it * 256 + tid;
            int row = idx >> 5, seg = idx & 31;
            CP_ASYNC16(qdst + ((uint32_t)row*136 + seg*4)*4, qp + (size_t)row*NQ_ + seg*4);
        }
        CP_COMMIT();
        CP_WAIT(0);
        __syncthreads();
    }

    uint32_t qf[16][4];
    {
        const float* qs = Ks0 + (wm*16 + g)*136 + 2*q4;
        #pragma unroll
        for (int ks = 0; ks < 16; ++ks) {
            float2 t0 = *(const float2*)(qs + ks*8);
            float2 t1 = *(const float2*)(qs + ks*8 + 8*136);
            qf[ks][0] = rna_tf32_u(t0.x * scale);
            qf[ks][2] = rna_tf32_u(t0.y * scale);
            qf[ks][1] = rna_tf32_u(t1.x * scale);
            qf[ks][3] = rna_tf32_u(t1.y * scale);
        }
    }
    __syncthreads();

    const int njt = 2*qt + 2;

    auto load_k = [&](int jt) {
        uint32_t kd = sb + (uint32_t)((jt & 1) ? 2*FKV : FKV) * 4;
        const float* kp = K + (size_t)(b*T_ + jt*64) * NKV_ + kvh*128;
        #pragma unroll
        for (int it = 0; it < 8; ++it) {
            int idx = it * 256 + tid;
            int row = idx >> 5, seg = idx & 31;
            CP_ASYNC16(kd + ((uint32_t)row*136 + seg*4)*4, kp + (size_t)row*NKV_ + seg*4);
        }
    };
    auto load_v = [&](int jt) {
        uint32_t vd = sb + (uint32_t)((jt & 1) ? 4*FKV : 3*FKV) * 4;
        const float* vp = V + (size_t)(b*T_ + jt*64) * NKV_ + kvh*128;
        #pragma unroll
        for (int it = 0; it < 8; ++it) {
            int idx = it * 256 + tid;
            int row = idx >> 5, seg = idx & 31;
            CP_ASYNC16(vd + ((uint32_t)row*136 + seg*4)*4, vp + (size_t)row*NKV_ + seg*4);
        }
    };

    load_k(0); load_v(0); CP_COMMIT();
    load_k(1); load_v(1); CP_COMMIT();

    float m0 = -1e30f, m1 = -1e30f, l0 = 0.f, l1 = 0.f;
    float O[16][4];
    #pragma unroll
    for (int nf = 0; nf < 16; ++nf)
        #pragma unroll
        for (int e = 0; e < 4; ++e) O[nf][e] = 0.f;

    const int row_g0 = qt*128 + wm*16 + g;
    float* Prow = Psm + (wm*16 + g)*68;

    for (int jt = 0; jt < njt; ++jt) {
        const int cur = jt & 1;
        if (jt == 0) { CP_WAIT(1); } else { CP_WAIT(2); }
        __syncthreads();

        const float* Kc = cur ? Ks1 : Ks0;
        const float* Vc = cur ? Vs1 : Vs0;

        float S[8][4];
        #pragma unroll
        for (int nf = 0; nf < 8; ++nf)
            #pragma unroll
            for (int e = 0; e < 4; ++e) S[nf][e] = 0.f;

        #pragma unroll
        for (int ks = 0; ks < 16; ++ks) {
            const float* kb = Kc + g*136 + ks*8 + 2*q4;
            #pragma unroll
            for (int nf = 0; nf < 8; ++nf) {
                float2 t = *(const float2*)(kb + nf*8*136);
                uint32_t bb[2] = { __float_as_uint(t.x), __float_as_uint(t.y) };
                MMA_TF32(S[nf], qf[ks], bb);
            }
        }

        if (jt >= 2*qt) {
            const int colb = jt*64 + 2*q4;
            #pragma unroll
            for (int nf = 0; nf < 8; ++nf) {
                const int c0 = colb + nf*8;
                if (c0     > row_g0)     S[nf][0] = -1e30f;
                if (c0 + 1 > row_g0)     S[nf][1] = -1e30f;
                if (c0     > row_g0 + 8) S[nf][2] = -1e30f;
                if (c0 + 1 > row_g0 + 8) S[nf][3] = -1e30f;
            }
        }

        float rm0 = -1e30f, rm1 = -1e30f;
        #pragma unroll
        for (int nf = 0; nf < 8; ++nf) {
            rm0 = fmaxf(rm0, fmaxf(S[nf][0], S[nf][1]));
            rm1 = fmaxf(rm1, fmaxf(S[nf][2], S[nf][3]));
        }
        rm0 = fmaxf(rm0, __shfl_xor_sync(0xffffffffu, rm0, 1));
        rm0 = fmaxf(rm0, __shfl_xor_sync(0xffffffffu, rm0, 2));
        rm1 = fmaxf(rm1, __shfl_xor_sync(0xffffffffu, rm1, 1));
        rm1 = fmaxf(rm1, __shfl_xor_sync(0xffffffffu, rm1, 2));

        const float mn0 = fmaxf(m0, rm0), mn1 = fmaxf(m1, rm1);
        const float corr0 = __expf(m0 - mn0), corr1 = __expf(m1 - mn1);
        m0 = mn0; m1 = mn1;

        float rs0 = 0.f, rs1 = 0.f;
        #pragma unroll
        for (int nf = 0; nf < 8; ++nf) {
            S[nf][0] = __expf(S[nf][0] - mn0);
            S[nf][1] = __expf(S[nf][1] - mn0);
            S[nf][2] = __expf(S[nf][2] - mn1);
            S[nf][3] = __expf(S[nf][3] - mn1);
            rs0 += S[nf][0] + S[nf][1];
            rs1 += S[nf][2] + S[nf][3];
        }
        rs0 += __shfl_xor_sync(0xffffffffu, rs0, 1);
        rs0 += __shfl_xor_sync(0xffffffffu, rs0, 2);
        rs1 += __shfl_xor_sync(0xffffffffu, rs1, 1);
        rs1 += __shfl_xor_sync(0xffffffffu, rs1, 2);
        l0 = l0*corr0 + rs0;
        l1 = l1*corr1 + rs1;

        #pragma unroll
        for (int nf = 0; nf < 16; ++nf) {
            O[nf][0] *= corr0; O[nf][1] *= corr0;
            O[nf][2] *= corr1; O[nf][3] *= corr1;
        }

        #pragma unroll
        for (int nf = 0; nf < 8; ++nf) {
            const int c = nf*8 + 2*q4;
            *(float2*)(Prow + c)        = make_float2(rna_tf32(S[nf][0]), rna_tf32(S[nf][1]));
            *(float2*)(Prow + 8*68 + c) = make_float2(rna_tf32(S[nf][2]), rna_tf32(S[nf][3]));
        }
        __syncthreads();

        if (jt + 2 < njt) load_k(jt + 2);
        CP_COMMIT();

        #pragma unroll
        for (int ks = 0; ks < 8; ++ks) {
            uint32_t a[4];
            a[0] = __float_as_uint(Prow[ks*8 + q4]);
            a[2] = __float_as_uint(Prow[ks*8 + q4 + 4]);
            a[1] = __float_as_uint(Prow[8*68 + ks*8 + q4]);
            a[3] = __float_as_uint(Prow[8*68 + ks*8 + q4 + 4]);
            const float* vb = Vc + (ks*8 + q4)*136 + g;
            #pragma unroll
            for (int nf = 0; nf < 16; ++nf) {
                uint32_t bb[2] = { __float_as_uint(vb[nf*8]),
                                   __float_as_uint(vb[nf*8 + 4*136]) };
                MMA_TF32(O[nf], a, bb);
            }
        }
        __syncthreads();

        if (jt + 2 < njt) load_v(jt + 2);
        CP_COMMIT();
    }

    const float inv0 = 1.0f / l0;
    const float inv1 = 1.0f / l1;
    float* o0 = Out + (size_t)(b*T_ + row_g0)     * NQ_ + h*128 + 2*q4;
    float* o1 = Out + (size_t)(b*T_ + row_g0 + 8) * NQ_ + h*128 + 2*q4;
    #pragma unroll
    for (int nf = 0; nf < 16; ++nf) {
        *(float2*)(o0 + nf*8) = make_float2(rna_tf32(O[nf][0]*inv0), rna_tf32(O[nf][1]*inv0));
        *(float2*)(o1 + nf*8) = make_float2(rna_tf32(O[nf][2]*inv1), rna_tf32(O[nf][3]*inv1));
    }
}

// ---------------------------------------------------------------------------
__global__ void zero_tail_kernel(float* __restrict__ out, long start, long total) {
    long idx = start + blockIdx.x * (long)blockDim.x + threadIdx.x;
    if (idx < total) out[idx] = 0.f;
}

// ---------------------------------------------------------------------------
extern "C" void kernel_launch(void* const* d_in, const int* in_sizes, int n_in,
                              void* d_out, int out_size) {
    const float* x  = (const float*)d_in[0];
    const float* Wq = (const float*)d_in[1];
    const float* Wk = (const float*)d_in[2];
    const float* Wv = (const float*)d_in[3];
    const float* Wo = (const float*)d_in[4];
    float* out = (float*)d_out;

    float *q, *k, *v, *att, *xr, *wq, *wk, *wv, *wo, *rope;
    cudaGetSymbolAddress((void**)&q,    g_q);
    cudaGetSymbolAddress((void**)&k,    g_k);
    cudaGetSymbolAddress((void**)&v,    g_v);
    cudaGetSymbolAddress((void**)&att,  g_att);
    cudaGetSymbolAddress((void**)&xr,   g_xr);
    cudaGetSymbolAddress((void**)&wq,   g_wq);
    cudaGetSymbolAddress((void**)&wk,   g_wk);
    cudaGetSymbolAddress((void**)&wv,   g_wv);
    cudaGetSymbolAddress((void**)&wo,   g_wo);
    cudaGetSymbolAddress((void**)&rope, g_rope);

    rope_table_kernel<<<(T_*64 + 255)/256, 256>>>(rope);

    const long total4 = ((long)M_*DM_ + (long)NQ_*DM_ + 2L*NKV_*DM_ + (long)DM_*NQ_) / 4;
    round5_kernel<<<(int)((total4 + 255) / 256), 256>>>(x, Wq, Wk, Wv, Wo,
                                                        xr, wq, wk, wv, wo);

    const int gsm = 2 * STAGE_B;   // 81920 B -> two CTAs per SM
    cudaFuncSetAttribute((tc_gemm<true , false>), cudaFuncAttributeMaxDynamicSharedMemorySize, gsm);
    cudaFuncSetAttribute((tc_gemm<true , true >), cudaFuncAttributeMaxDynamicSharedMemorySize, gsm);
    cudaFuncSetAttribute((tc_gemm<false, true >), cudaFuncAttributeMaxDynamicSharedMemorySize, gsm);
    cudaFuncSetAttribute((tc_gemm<false, false>), cudaFuncAttributeMaxDynamicSharedMemorySize, gsm);

    dim3 blk(128);   // 4-warp CTAs
    // q: fp32 out (flash scales+rounds it); k,v: tf32-rounded at write
    tc_gemm<true , false><<<dim3(NQ_ /128, M_/128), blk, gsm>>>(xr, wq, q, M_, NQ_,  DM_, rope);
    tc_gemm<true , true ><<<dim3(NKV_/128, M_/128), blk, gsm>>>(xr, wk, k, M_, NKV_, DM_, rope);
    tc_gemm<false, true ><<<dim3(NKV_/128, M_/128), blk, gsm>>>(xr, wv, v, M_, NKV_, DM_, nullptr);

    const int fsm = 5 * FKV * 4;   // 174080 B
    cudaFuncSetAttribute(flash_tc, cudaFuncAttributeMaxDynamicSharedMemorySize, fsm);
    flash_tc<<<dim3(T_/128, H_, B_), dim3(256), fsm>>>(q, k, v, att);

    tc_gemm<false, false><<<dim3(NQ_/128, M_/128), blk, gsm>>>(att, wo, out, M_, NQ_, DM_, nullptr);

    long main_elems = (long)M_ * NQ_;
    long tail = (long)out_size - main_elems;
    if (tail > 0) {
        int nb = (int)((tail + 255) / 256);
        zero_tail_kernel<<<nb, 256>>>(out, main_elems, (long)out_size);
    }
}

// round 10
// speedup vs baseline: 1.2161x; 1.0037x over previous
#include <cuda_runtime.h>
#include <math.h>
#include <stdint.h>

// Problem constants
#define B_    4
#define T_    2048
#define DM_   2048
#define H_    16
#define HKV_  4
#define D_    128
#define M_    (B_*T_)      // 8192 tokens
#define NQ_   (H_*D_)      // 2048
#define NKV_  (HKV_*D_)    // 512

// Scratch (device globals: allocation-free per harness rules)
__device__ float g_q  [M_*NQ_];
__device__ float g_k  [M_*NKV_];
__device__ float g_v  [M_*NKV_];
__device__ float g_att[M_*NQ_];
__device__ float g_xr [M_*DM_];
__device__ float g_wq [NQ_*DM_];
__device__ float g_wk [NKV_*DM_];
__device__ float g_wv [NKV_*DM_];
__device__ float g_wo [DM_*NQ_];
__device__ float g_rope[T_*64*2];

// ---------------------------------------------------------------------------
// Helpers
// ---------------------------------------------------------------------------
__device__ __forceinline__ uint32_t smem_u32(const void* p) {
    uint32_t a;
    asm("{ .reg .u64 t; cvta.to.shared.u64 t, %1; cvt.u32.u64 %0, t; }" : "=r"(a) : "l"(p));
    return a;
}
__device__ __forceinline__ float rna_tf32(float v) {
    uint32_t b;
    asm("cvt.rna.tf32.f32 %0, %1;" : "=r"(b) : "f"(v));
    return __uint_as_float(b);
}
__device__ __forceinline__ uint32_t rna_tf32_u(float v) {
    uint32_t b;
    asm("cvt.rna.tf32.f32 %0, %1;" : "=r"(b) : "f"(v));
    return b;
}

#define CP_ASYNC16(dst, src) \
    asm volatile("cp.async.cg.shared.global [%0], [%1], 16;" :: "r"(dst), "l"(src) : "memory")
#define CP_COMMIT()  asm volatile("cp.async.commit_group;" ::: "memory")
#define CP_WAIT(n)   asm volatile("cp.async.wait_group %0;" :: "n"(n) : "memory")

// mma.sync m16n8k8 tf32 (family-portable)
#define MMA_TF32(c, a, b) \
    asm volatile("mma.sync.aligned.m16n8k8.row.col.f32.tf32.tf32.f32 " \
        "{%0,%1,%2,%3}, {%4,%5,%6,%7}, {%8,%9}, {%0,%1,%2,%3};" \
        : "+f"((c)[0]), "+f"((c)[1]), "+f"((c)[2]), "+f"((c)[3]) \
        : "r"((a)[0]), "r"((a)[1]), "r"((a)[2]), "r"((a)[3]), \
          "r"((b)[0]), "r"((b)[1]))

// ---------------------------------------------------------------------------
// Prepass kernels (split so the merged qkv GEMM is launch #6 for ncu -s 5)
// ---------------------------------------------------------------------------
__global__ void round_one_kernel(const float* __restrict__ in, float* __restrict__ out, long n4) {
    long i = blockIdx.x * (long)blockDim.x + threadIdx.x;
    if (i >= n4) return;
    float4 v = ((const float4*)in)[i];
    v.x = rna_tf32(v.x); v.y = rna_tf32(v.y); v.z = rna_tf32(v.z); v.w = rna_tf32(v.w);
    ((float4*)out)[i] = v;
}

__global__ void round_wqkv_kernel(const float* __restrict__ wq, const float* __restrict__ wk,
                                  const float* __restrict__ wv,
                                  float* __restrict__ owq, float* __restrict__ owk,
                                  float* __restrict__ owv)
{
    const long n_q  = (long)NQ_ * DM_ / 4;
    const long n_kv = (long)NKV_* DM_ / 4;
    long j = blockIdx.x * (long)blockDim.x + threadIdx.x;
    const float* src; float* dst;
    if (j < n_q)                 { src = wq; dst = owq; }
    else if ((j -= n_q) < n_kv)  { src = wk; dst = owk; }
    else if ((j -= n_kv) < n_kv) { src = wv; dst = owv; }
    else return;
    float4 v = ((const float4*)src)[j];
    v.x = rna_tf32(v.x); v.y = rna_tf32(v.y); v.z = rna_tf32(v.z); v.w = rna_tf32(v.w);
    ((float4*)dst)[j] = v;
}

__global__ void rope_table_kernel(float* __restrict__ tab, int tbase) {
    int idx = blockIdx.x * blockDim.x + threadIdx.x;
    if (idx >= (T_/2) * 64) return;
    int t = tbase + (idx >> 6), f = idx & 63;
    double invf = exp(-((double)f / 64.0) * log(10000.0));
    float ang = (float)t * (float)invf;
    tab[(t*64 + f)*2 + 0] = (float)cos((double)ang);
    tab[(t*64 + f)*2 + 1] = (float)sin((double)ang);
}

// ---------------------------------------------------------------------------
// Shared GEMM mainloop pieces (CTA 128x128x32, 4 warps, 64x64 warp tiles,
// 2 CTAs/SM). SINGLE barrier per chunk; next chunk's cp.async issued AFTER
// the barrier so the whole chunk's MMA time hides the load latency (this is
// the flash_tc pattern — flash achieves ~165 TF/s vs the old loop's 133).
// ---------------------------------------------------------------------------
#define STAGE_F 10240
#define STAGE_B (STAGE_F*4)

struct GemmCore {
    const float* Ab;
    const float* Wb;
    float* smf;
    uint32_t sbase;
    int tid, lane, warp_m, warp_n, g, q4;

    __device__ __forceinline__ void load_stage(int s, int kt, int K) const {
        uint32_t aS = sbase + s * STAGE_B;
        uint32_t bS = aS + 20480;
        const float* ap = Ab + kt * 32;
        const float* wp = Wb + kt * 32;
        #pragma unroll
        for (int it = 0; it < 8; ++it) {
            int idx = it * 128 + tid;
            int row = idx >> 3, seg = idx & 7;
            uint32_t so = (uint32_t)row * 160 + (uint32_t)seg * 16;
            CP_ASYNC16(aS + so, ap + (size_t)row * K + seg * 4);
            CP_ASYNC16(bS + so, wp + (size_t)row * K + seg * 4);
        }
    }

    __device__ __forceinline__ void load_frags(const float* As_, const float* Bs_,
                                               int ks, uint32_t* a, uint32_t* b) const {
        const int col = ks * 8 + 2 * q4;
        #pragma unroll
        for (int ni = 0; ni < 8; ++ni) {
            float2 t = *(const float2*)&Bs_[(ni * 8 + g) * 40 + col];
            b[ni*2]   = __float_as_uint(t.x);
            b[ni*2+1] = __float_as_uint(t.y);
        }
        #pragma unroll
        for (int mi = 0; mi < 4; ++mi) {
            float2 t0 = *(const float2*)&As_[(mi * 16 + g) * 40 + col];
            float2 t1 = *(const float2*)&As_[(mi * 16 + g + 8) * 40 + col];
            a[mi*4+0] = __float_as_uint(t0.x);
            a[mi*4+2] = __float_as_uint(t0.y);
            a[mi*4+1] = __float_as_uint(t1.x);
            a[mi*4+3] = __float_as_uint(t1.y);
        }
    }

    __device__ __forceinline__ void mainloop(float acc[4][8][4], int K) const {
        const int KT = K >> 5;
        load_stage(0, 0, K);
        CP_COMMIT();
        for (int kt = 0; kt < KT; ++kt) {
            const int cur = kt & 1;
            CP_WAIT(0);          // chunk kt resident (issued one full chunk ago)
            __syncthreads();     // publish; all warps done reading buf cur^1
            if (kt + 1 < KT) {   // overlap next chunk's loads with this chunk's MMAs
                load_stage(cur ^ 1, kt + 1, K);
                CP_COMMIT();
            }
            const float* As_ = smf + cur * STAGE_F + warp_m * (64 * 40);
            const float* Bs_ = smf + cur * STAGE_F + 5120 + warp_n * (64 * 40);

            uint32_t aF[2][16], bF[2][16];
            load_frags(As_, Bs_, 0, aF[0], bF[0]);
            #pragma unroll
            for (int ks = 0; ks < 4; ++ks) {
                const int cb = ks & 1;
                if (ks < 3) load_frags(As_, Bs_, ks + 1, aF[cb ^ 1], bF[cb ^ 1]);
                #pragma unroll
                for (int mi = 0; mi < 4; ++mi)
                    #pragma unroll
                    for (int ni = 0; ni < 8; ++ni)
                        MMA_TF32(acc[mi][ni], &aF[cb][mi*4], &bF[cb][ni*2]);
            }
        }
        __syncthreads();   // acc complete; stage smem reusable by epilogue
    }

    __device__ __forceinline__ void epilogue_plain(float acc[4][8][4], float* C,
                                                   int N, int row0, int col0, bool rnd) const {
        #pragma unroll
        for (int mi = 0; mi < 4; ++mi) {
            const int r = row0 + warp_m * 64 + mi * 16 + g;
            #pragma unroll
            for (int ni = 0; ni < 8; ++ni) {
                const int c = col0 + warp_n * 64 + ni * 8 + q4 * 2;
                float e0 = acc[mi][ni][0], e1 = acc[mi][ni][1];
                float e2 = acc[mi][ni][2], e3 = acc[mi][ni][3];
                if (rnd) { e0 = rna_tf32(e0); e1 = rna_tf32(e1); e2 = rna_tf32(e2); e3 = rna_tf32(e3); }
                *(float2*)&C[(size_t)r * N + c]       = make_float2(e0, e1);
                *(float2*)&C[(size_t)(r + 8) * N + c] = make_float2(e2, e3);
            }
        }
    }

    __device__ __forceinline__ void epilogue_fuse(float acc[4][8][4], float* C,
                                                  int N, int row0, int col0,
                                                  const float* rope, bool rnd) const {
        float* Cs = smf;   // 128*129 floats; stage buffers dead
        #pragma unroll
        for (int mi = 0; mi < 4; ++mi) {
            const int r = warp_m * 64 + mi * 16 + g;
            #pragma unroll
            for (int ni = 0; ni < 8; ++ni) {
                const int c = warp_n * 64 + ni * 8 + q4 * 2;
                Cs[r * 129 + c]           = acc[mi][ni][0];
                Cs[r * 129 + c + 1]       = acc[mi][ni][1];
                Cs[(r + 8) * 129 + c]     = acc[mi][ni][2];
                Cs[(r + 8) * 129 + c + 1] = acc[mi][ni][3];
            }
        }
        __syncthreads();
        {
            const int row = row0 + tid;          // 128 threads = 128 rows
            const float* cr = Cs + tid * 129;
            float ss = 0.f;
            #pragma unroll 16
            for (int j = 0; j < 128; ++j) ss += cr[j] * cr[j];
            const float sc = rsqrtf(ss * (1.0f/128.0f) + 1.1920928955078125e-07f);
            const float* rp = rope + (row & (T_ - 1)) * 128;
            float* op = C + (size_t)row * N + col0;
            #pragma unroll
            for (int f4 = 0; f4 < 64; f4 += 4) {
                float4 o1, o2;
                #pragma unroll
                for (int e = 0; e < 4; ++e) {
                    const int f = f4 + e;
                    const float v1 = cr[f] * sc;
                    const float v2 = cr[f + 64] * sc;
                    const float cz = rp[2*f], sz = rp[2*f + 1];
                    float r1 =  v1 * cz + v2 * sz;
                    float r2 = -v1 * sz + v2 * cz;
                    if (rnd) { r1 = rna_tf32(r1); r2 = rna_tf32(r2); }
                    (&o1.x)[e] = r1;
                    (&o2.x)[e] = r2;
                }
                *(float4*)(op + f4)      = o1;
                *(float4*)(op + f4 + 64) = o2;
            }
        }
        __syncthreads();
    }
};

// ---------------------------------------------------------------------------
// Merged q/k/v projection GEMM: one launch, grid (24, 64).
// bx 0..15 -> q (fuse, no round); 16..19 -> k (fuse, round); 20..23 -> v (round).
// ---------------------------------------------------------------------------
__global__ __launch_bounds__(128, 2)
void tc_gemm_qkv(const float* __restrict__ A,
                 const float* __restrict__ Wq, const float* __restrict__ Wk,
                 const float* __restrict__ Wv,
                 float* __restrict__ Cq, float* __restrict__ Ck, float* __restrict__ Cv,
                 const float* __restrict__ rope)
{
    extern __shared__ float smf[];
    const int bxg = blockIdx.x, by = blockIdx.y;

    const float* Wbase; float* Cout; int N, bxl; bool fuse, rnd;
    if (bxg < 16)      { Wbase = Wq; Cout = Cq; N = NQ_;  bxl = bxg;      fuse = true;  rnd = false; }
    else if (bxg < 20) { Wbase = Wk; Cout = Ck; N = NKV_; bxl = bxg - 16; fuse = true;  rnd = true;  }
    else               { Wbase = Wv; Cout = Cv; N = NKV_; bxl = bxg - 20; fuse = false; rnd = true;  }

    GemmCore core;
    core.smf = smf; core.sbase = smem_u32(smf);
    core.tid = threadIdx.x; core.lane = core.tid & 31;
    const int wid = core.tid >> 5;
    core.warp_m = wid >> 1; core.warp_n = wid & 1;
    core.g = core.lane >> 2; core.q4 = core.lane & 3;
    core.Ab = A + (size_t)(by * 128) * DM_;
    core.Wb = Wbase + (size_t)(bxl * 128) * DM_;

    float acc[4][8][4];
    #pragma unroll
    for (int mi = 0; mi < 4; ++mi)
        #pragma unroll
        for (int ni = 0; ni < 8; ++ni)
            #pragma unroll
            for (int e = 0; e < 4; ++e) acc[mi][ni][e] = 0.f;

    core.mainloop(acc, DM_);

    if (fuse) core.epilogue_fuse (acc, Cout, N, by * 128, bxl * 128, rope, rnd);
    else      core.epilogue_plain(acc, Cout, N, by * 128, bxl * 128, rnd);
}

// Plain GEMM for the Wo projection (no fuse, no rounding).
__global__ __launch_bounds__(128, 2)
void tc_gemm_wo(const float* __restrict__ A, const float* __restrict__ W,
                float* __restrict__ C)
{
    extern __shared__ float smf[];
    const int bx = blockIdx.x, by = blockIdx.y;

    GemmCore core;
    core.smf = smf; core.sbase = smem_u32(smf);
    core.tid = threadIdx.x; core.lane = core.tid & 31;
    const int wid = core.tid >> 5;
    core.warp_m = wid >> 1; core.warp_n = wid & 1;
    core.g = core.lane >> 2; core.q4 = core.lane & 3;
    core.Ab = A + (size_t)(by * 128) * DM_;
    core.Wb = W + (size_t)(bx * 128) * DM_;

    float acc[4][8][4];
    #pragma unroll
    for (int mi = 0; mi < 4; ++mi)
        #pragma unroll
        for (int ni = 0; ni < 8; ++ni)
            #pragma unroll
            for (int e = 0; e < 4; ++e) acc[mi][ni][e] = 0.f;

    core.mainloop(acc, DM_);
    core.epilogue_plain(acc, C, NQ_, by * 128, bx * 128, false);
}

// ---------------------------------------------------------------------------
// Tensor-core flash attention (tf32 mma.sync), causal, GQA. (R4/R6, proven)
// ---------------------------------------------------------------------------
#define FKV 8704   // floats per K/V buffer (64*136)

__global__ __launch_bounds__(256, 1)
void flash_tc(const float* __restrict__ Q, const float* __restrict__ K,
              const float* __restrict__ V, float* __restrict__ Out)
{
    extern __shared__ float sm[];
    float* Psm = sm;                       // 128 x 68
    float* Ks0 = sm + FKV;                 // 64 x 136
    float* Ks1 = sm + 2*FKV;
    float* Vs0 = sm + 3*FKV;
    float* Vs1 = sm + 4*FKV;
    const uint32_t sb = smem_u32(sm);

    const int qt  = (int)gridDim.x - 1 - (int)blockIdx.x;
    const int h   = blockIdx.y;
    const int b   = blockIdx.z;
    const int kvh = h >> 2;
    const int tid = threadIdx.x;
    const int lane = tid & 31;
    const int wm   = tid >> 5;
    const int g    = lane >> 2;
    const int q4   = lane & 3;

    const float scale = 0.08838834764831843f;

    {   // stage Q tile (128 x 128) into K0+K1 region, stride 136
        const float* qp = Q + (size_t)(b*T_ + qt*128) * NQ_ + h*128;
        uint32_t qdst = sb + FKV*4;
        #pragma unroll
        for (int it = 0; it < 16; ++it) {
            int idx = it * 256 + tid;
            int row = idx >> 5, seg = idx & 31;
            CP_ASYNC16(qdst + ((uint32_t)row*136 + seg*4)*4, qp + (size_t)row*NQ_ + seg*4);
        }
        CP_COMMIT();
        CP_WAIT(0);
        __syncthreads();
    }

    uint32_t qf[16][4];
    {
        const float* qs = Ks0 + (wm*16 + g)*136 + 2*q4;
        #pragma unroll
        for (int ks = 0; ks < 16; ++ks) {
            float2 t0 = *(const float2*)(qs + ks*8);
            float2 t1 = *(const float2*)(qs + ks*8 + 8*136);
            qf[ks][0] = rna_tf32_u(t0.x * scale);
            qf[ks][2] = rna_tf32_u(t0.y * scale);
            qf[ks][1] = rna_tf32_u(t1.x * scale);
            qf[ks][3] = rna_tf32_u(t1.y * scale);
        }
    }
    __syncthreads();

    const int njt = 2*qt + 2;

    auto load_k = [&](int jt) {
        uint32_t kd = sb + (uint32_t)((jt & 1) ? 2*FKV : FKV) * 4;
        const float* kp = K + (size_t)(b*T_ + jt*64) * NKV_ + kvh*128;
        #pragma unroll
        for (int it = 0; it < 8; ++it) {
            int idx = it * 256 + tid;
            int row = idx >> 5, seg = idx & 31;
            CP_ASYNC16(kd + ((uint32_t)row*136 + seg*4)*4, kp + (size_t)row*NKV_ + seg*4);
        }
    };
    auto load_v = [&](int jt) {
        uint32_t vd = sb + (uint32_t)((jt & 1) ? 4*FKV : 3*FKV) * 4;
        const float* vp = V + (size_t)(b*T_ + jt*64) * NKV_ + kvh*128;
        #pragma unroll
        for (int it = 0; it < 8; ++it) {
            int idx = it * 256 + tid;
            int row = idx >> 5, seg = idx & 31;
            CP_ASYNC16(vd + ((uint32_t)row*136 + seg*4)*4, vp + (size_t)row*NKV_ + seg*4);
        }
    };

    load_k(0); load_v(0); CP_COMMIT();
    load_k(1); load_v(1); CP_COMMIT();

    float m0 = -1e30f, m1 = -1e30f, l0 = 0.f, l1 = 0.f;
    float O[16][4];
    #pragma unroll
    for (int nf = 0; nf < 16; ++nf)
        #pragma unroll
        for (int e = 0; e < 4; ++e) O[nf][e] = 0.f;

    const int row_g0 = qt*128 + wm*16 + g;
    float* Prow = Psm + (wm*16 + g)*68;

    for (int jt = 0; jt < njt; ++jt) {
        const int cur = jt & 1;
        if (jt == 0) { CP_WAIT(1); } else { CP_WAIT(2); }
        __syncthreads();

        const float* Kc = cur ? Ks1 : Ks0;
        const float* Vc = cur ? Vs1 : Vs0;

        float S[8][4];
        #pragma unroll
        for (int nf = 0; nf < 8; ++nf)
            #pragma unroll
            for (int e = 0; e < 4; ++e) S[nf][e] = 0.f;

        #pragma unroll
        for (int ks = 0; ks < 16; ++ks) {
            const float* kb = Kc + g*136 + ks*8 + 2*q4;
            #pragma unroll
            for (int nf = 0; nf < 8; ++nf) {
                float2 t = *(const float2*)(kb + nf*8*136);
                uint32_t bb[2] = { __float_as_uint(t.x), __float_as_uint(t.y) };
                MMA_TF32(S[nf], qf[ks], bb);
            }
        }

        if (jt >= 2*qt) {
            const int colb = jt*64 + 2*q4;
            #pragma unroll
            for (int nf = 0; nf < 8; ++nf) {
                const int c0 = colb + nf*8;
                if (c0     > row_g0)     S[nf][0] = -1e30f;
                if (c0 + 1 > row_g0)     S[nf][1] = -1e30f;
                if (c0     > row_g0 + 8) S[nf][2] = -1e30f;
                if (c0 + 1 > row_g0 + 8) S[nf][3] = -1e30f;
            }
        }

        float rm0 = -1e30f, rm1 = -1e30f;
        #pragma unroll
        for (int nf = 0; nf < 8; ++nf) {
            rm0 = fmaxf(rm0, fmaxf(S[nf][0], S[nf][1]));
            rm1 = fmaxf(rm1, fmaxf(S[nf][2], S[nf][3]));
        }
        rm0 = fmaxf(rm0, __shfl_xor_sync(0xffffffffu, rm0, 1));
        rm0 = fmaxf(rm0, __shfl_xor_sync(0xffffffffu, rm0, 2));
        rm1 = fmaxf(rm1, __shfl_xor_sync(0xffffffffu, rm1, 1));
        rm1 = fmaxf(rm1, __shfl_xor_sync(0xffffffffu, rm1, 2));

        const float mn0 = fmaxf(m0, rm0), mn1 = fmaxf(m1, rm1);
        const float corr0 = __expf(m0 - mn0), corr1 = __expf(m1 - mn1);
        m0 = mn0; m1 = mn1;

        float rs0 = 0.f, rs1 = 0.f;
        #pragma unroll
        for (int nf = 0; nf < 8; ++nf) {
            S[nf][0] = __expf(S[nf][0] - mn0);
            S[nf][1] = __expf(S[nf][1] - mn0);
            S[nf][2] = __expf(S[nf][2] - mn1);
            S[nf][3] = __expf(S[nf][3] - mn1);
            rs0 += S[nf][0] + S[nf][1];
            rs1 += S[nf][2] + S[nf][3];
        }
        rs0 += __shfl_xor_sync(0xffffffffu, rs0, 1);
        rs0 += __shfl_xor_sync(0xffffffffu, rs0, 2);
        rs1 += __shfl_xor_sync(0xffffffffu, rs1, 1);
        rs1 += __shfl_xor_sync(0xffffffffu, rs1, 2);
        l0 = l0*corr0 + rs0;
        l1 = l1*corr1 + rs1;

        #pragma unroll
        for (int nf = 0; nf < 16; ++nf) {
            O[nf][0] *= corr0; O[nf][1] *= corr0;
            O[nf][2] *= corr1; O[nf][3] *= corr1;
        }

        #pragma unroll
        for (int nf = 0; nf < 8; ++nf) {
            const int c = nf*8 + 2*q4;
            *(float2*)(Prow + c)        = make_float2(rna_tf32(S[nf][0]), rna_tf32(S[nf][1]));
            *(float2*)(Prow + 8*68 + c) = make_float2(rna_tf32(S[nf][2]), rna_tf32(S[nf][3]));
        }
        __syncthreads();

        if (jt + 2 < njt) load_k(jt + 2);
        CP_COMMIT();

        #pragma unroll
        for (int ks = 0; ks < 8; ++ks) {
            uint32_t a[4];
            a[0] = __float_as_uint(Prow[ks*8 + q4]);
            a[2] = __float_as_uint(Prow[ks*8 + q4 + 4]);
            a[1] = __float_as_uint(Prow[8*68 + ks*8 + q4]);
            a[3] = __float_as_uint(Prow[8*68 + ks*8 + q4 + 4]);
            const float* vb = Vc + (ks*8 + q4)*136 + g;
            #pragma unroll
            for (int nf = 0; nf < 16; ++nf) {
                uint32_t bb[2] = { __float_as_uint(vb[nf*8]),
                                   __float_as_uint(vb[nf*8 + 4*136]) };
                MMA_TF32(O[nf], a, bb);
            }
        }
        __syncthreads();

        if (jt + 2 < njt) load_v(jt + 2);
        CP_COMMIT();
    }

    const float inv0 = 1.0f / l0;
    const float inv1 = 1.0f / l1;
    float* o0 = Out + (size_t)(b*T_ + row_g0)     * NQ_ + h*128 + 2*q4;
    float* o1 = Out + (size_t)(b*T_ + row_g0 + 8) * NQ_ + h*128 + 2*q4;
    #pragma unroll
    for (int nf = 0; nf < 16; ++nf) {
        *(float2*)(o0 + nf*8) = make_float2(rna_tf32(O[nf][0]*inv0), rna_tf32(O[nf][1]*inv0));
        *(float2*)(o1 + nf*8) = make_float2(rna_tf32(O[nf][2]*inv1), rna_tf32(O[nf][3]*inv1));
    }
}

// ---------------------------------------------------------------------------
__global__ void zero_tail_kernel(float* __restrict__ out, long start, long total) {
    long idx = start + blockIdx.x * (long)blockDim.x + threadIdx.x;
    if (idx < total) out[idx] = 0.f;
}

// ---------------------------------------------------------------------------
extern "C" void kernel_launch(void* const* d_in, const int* in_sizes, int n_in,
                              void* d_out, int out_size) {
    const float* x  = (const float*)d_in[0];
    const float* Wq = (const float*)d_in[1];
    const float* Wk = (const float*)d_in[2];
    const float* Wv = (const float*)d_in[3];
    const float* Wo = (const float*)d_in[4];
    float* out = (float*)d_out;

    float *q, *k, *v, *att, *xr, *wq, *wk, *wv, *wo, *rope;
    cudaGetSymbolAddress((void**)&q,    g_q);
    cudaGetSymbolAddress((void**)&k,    g_k);
    cudaGetSymbolAddress((void**)&v,    g_v);
    cudaGetSymbolAddress((void**)&att,  g_att);
    cudaGetSymbolAddress((void**)&xr,   g_xr);
    cudaGetSymbolAddress((void**)&wq,   g_wq);
    cudaGetSymbolAddress((void**)&wk,   g_wk);
    cudaGetSymbolAddress((void**)&wv,   g_wv);
    cudaGetSymbolAddress((void**)&wo,   g_wo);
    cudaGetSymbolAddress((void**)&rope, g_rope);

    // Launch order (ncu -s 5 -c 1 profiles launch #6 = merged qkv GEMM):
    // 1 round_x, 2 round_wqkv, 3 round_wo, 4 rope_lo, 5 rope_hi,
    // 6 qkv GEMM, 7 flash, 8 Wo GEMM, 9 tail.
    round_one_kernel<<<(int)((M_*(long)DM_/4 + 255)/256), 256>>>(x, xr, M_*(long)DM_/4);
    const long wtot4 = ((long)NQ_*DM_ + 2L*NKV_*DM_) / 4;
    round_wqkv_kernel<<<(int)((wtot4 + 255)/256), 256>>>(Wq, Wk, Wv, wq, wk, wv);
    round_one_kernel<<<(int)((DM_*(long)NQ_/4 + 255)/256), 256>>>(Wo, wo, DM_*(long)NQ_/4);
    rope_table_kernel<<<((T_/2)*64 + 255)/256, 256>>>(rope, 0);
    rope_table_kernel<<<((T_/2)*64 + 255)/256, 256>>>(rope, T_/2);

    const int gsm = 2 * STAGE_B;   // 81920 B -> two CTAs per SM
    cudaFuncSetAttribute(tc_gemm_qkv, cudaFuncAttributeMaxDynamicSharedMemorySize, gsm);
    cudaFuncSetAttribute(tc_gemm_wo,  cudaFuncAttributeMaxDynamicSharedMemorySize, gsm);

    tc_gemm_qkv<<<dim3(24, M_/128), dim3(128), gsm>>>(xr, wq, wk, wv, q, k, v, rope);

    const int fsm = 5 * FKV * 4;   // 174080 B
    cudaFuncSetAttribute(flash_tc, cudaFuncAttributeMaxDynamicSharedMemorySize, fsm);
    flash_tc<<<dim3(T_/128, H_, B_), dim3(256), fsm>>>(q, k, v, att);

    tc_gemm_wo<<<dim3(NQ_/128, M_/128), dim3(128), gsm>>>(att, wo, out);

    long main_elems = (long)M_ * NQ_;
    long tail = (long)out_size - main_elems;
    if (tail > 0) {
        int nb = (int)((tail + 255) / 256);
        zero_tail_kernel<<<nb, 256>>>(out, main_elems, (long)out_size);
    }
}